// round 12
// baseline (speedup 1.0000x reference)
#include <cuda_runtime.h>
#include <cuda_fp16.h>
#include <math.h>
#include <float.h>

// ---------------------------------------------------------------------------
// Scattering2D (J=2, L=8, 224x224) B=16, C=3  + global max pool + linear.
// FFTs: symmetric-pair 7-point DFT per lane x radix-2 shuffle FFT across lanes.
// Low-pass (phi) stages are exact spatial separable Gaussian blurs.
// Second-order fold fused into the final 224-pass (coalesced); fold in fp16.
// Chain: SoA fp32 smem (pitch 115, conflict-free), reg-cached twiddles,
// and empirical psi1 row masks to skip dead rows (load+FFT+fold stores).
// ---------------------------------------------------------------------------

#define IMG224 (224*224)
#define IMG112 (112*112)
#define CPITCH 115                       // chain smem pitch (odd mod 32)

// ---- device global scratch -------------------------------------------------
__device__ float2  g_w224[224];
__device__ float   g_psi0[8*IMG224];     // j=0 Morlets @224
__device__ float   g_psi1[8*IMG224];     // j=1 Morlets @224
__device__ unsigned char g_rowmask[8*112]; // alive flags for folded psi1 rows
__device__ float   g_h0[21];             // spatial phi taps @224 (stride-4 path)
__device__ float   g_h1[11];             // spatial phi taps @112 (stride-2 path)
__device__ float2  g_xh[48*IMG224];      // fft2(x)
__device__ float2  g_s1buf[384*IMG224];  // scratch A
__device__ float2  g_s2buf[384*IMG224];  // scratch B
__device__ __half  g_u1h[384*IMG224];    // spatial u1 [TRANSPOSED layout] fp16
__device__ __half2 g_foldh[3456*IMG112]; // prefolded 112x112 chain inputs (fp16)
__device__ float   g_feat[48*81];        // scattering features

// ---- complex helpers -------------------------------------------------------
__device__ __forceinline__ float2 cmul(float2 a, float2 b){
    return make_float2(fmaf(a.x,b.x,-a.y*b.y), fmaf(a.x,b.y, a.y*b.x));
}
template<bool INV>
__device__ __forceinline__ float2 twid(int t){
    float2 w = g_w224[t];
    if (INV) w.y = -w.y;
    return w;
}
template<bool INV>
__device__ __forceinline__ float2 cmul_s(float2 a, float2 b){
    float by = INV ? -b.y : b.y;
    return make_float2(fmaf(a.x,b.x,-a.y*by), fmaf(a.x,by, a.y*b.x));
}

// ---- register-cached twiddles (forward sign; INV conjugates at use) --------
template<int LOGG>
struct TW {
    float2 w1, w2, w3;      // DFT-7 roots
    float2 lt[6];           // lane twiddles k=1..6
    float2 st[LOGG];        // shuffle-stage twiddles
    __device__ __forceinline__ void init(int gl){
        w1 = g_w224[32]; w2 = g_w224[64]; w3 = g_w224[96];
        const int ST = 224 / (7 << LOGG);
        #pragma unroll
        for (int k = 1; k < 7; k++) lt[k-1] = g_w224[gl*k*ST];
        int s = 0;
        #pragma unroll
        for (int m = (1 << LOGG)/2; m >= 1; m >>= 1)
            st[s++] = g_w224[(gl & (m-1)) * (224/(2*m))];
    }
};

// ---- core line FFT with register twiddles; smask = participating lanes -----
template<int LOGG, bool INV>
__device__ __forceinline__ void fft_regs_t(float2 a[7], int gl,
                                           const TW<LOGG>& tw, unsigned smask){
    const int G = 1 << LOGG;
    const int N = 7 * G;
    const float sg = INV ? -1.f : 1.f;
    float w1y = sg*tw.w1.y, w2y = sg*tw.w2.y, w3y = sg*tw.w3.y;
    float w1x = tw.w1.x,    w2x = tw.w2.x,    w3x = tw.w3.x;

    float2 a0 = a[0];
    float2 s1 = make_float2(a[1].x+a[6].x, a[1].y+a[6].y);
    float2 s2 = make_float2(a[2].x+a[5].x, a[2].y+a[5].y);
    float2 s3 = make_float2(a[3].x+a[4].x, a[3].y+a[4].y);
    float2 d1 = make_float2(a[1].x-a[6].x, a[1].y-a[6].y);
    float2 d2 = make_float2(a[2].x-a[5].x, a[2].y-a[5].y);
    float2 d3 = make_float2(a[3].x-a[4].x, a[3].y-a[4].y);

    float2 A[7];
    A[0] = make_float2(a0.x + s1.x + s2.x + s3.x,
                       a0.y + s1.y + s2.y + s3.y);
    {
        float px = fmaf(w1x,s1.x, fmaf(w2x,s2.x, fmaf(w3x,s3.x, a0.x)));
        float py = fmaf(w1x,s1.y, fmaf(w2x,s2.y, fmaf(w3x,s3.y, a0.y)));
        float qx = fmaf(w1y,d1.x, fmaf(w2y,d2.x, w3y*d3.x));
        float qy = fmaf(w1y,d1.y, fmaf(w2y,d2.y, w3y*d3.y));
        A[1] = make_float2(px - qy, py + qx);
        A[6] = make_float2(px + qy, py - qx);
    }
    {
        float px = fmaf(w2x,s1.x, fmaf(w3x,s2.x, fmaf(w1x,s3.x, a0.x)));
        float py = fmaf(w2x,s1.y, fmaf(w3x,s2.y, fmaf(w1x,s3.y, a0.y)));
        float qx = fmaf(w2y,d1.x, fmaf(-w3y,d2.x, -w1y*d3.x));
        float qy = fmaf(w2y,d1.y, fmaf(-w3y,d2.y, -w1y*d3.y));
        A[2] = make_float2(px - qy, py + qx);
        A[5] = make_float2(px + qy, py - qx);
    }
    {
        float px = fmaf(w3x,s1.x, fmaf(w1x,s2.x, fmaf(w2x,s3.x, a0.x)));
        float py = fmaf(w3x,s1.y, fmaf(w1x,s2.y, fmaf(w2x,s3.y, a0.y)));
        float qx = fmaf(w3y,d1.x, fmaf(-w1y,d2.x, w2y*d3.x));
        float qy = fmaf(w3y,d1.y, fmaf(-w1y,d2.y, w2y*d3.y));
        A[3] = make_float2(px - qy, py + qx);
        A[4] = make_float2(px + qy, py - qx);
    }

    #pragma unroll
    for (int k1 = 1; k1 < 7; k1++)
        A[k1] = cmul_s<INV>(A[k1], tw.lt[k1-1]);

    int si = 0;
    #pragma unroll
    for (int m = G/2; m >= 1; m >>= 1, si++){
        float2 w = tw.st[si];
        bool up = (gl & m) != 0;
        #pragma unroll
        for (int k1 = 0; k1 < 7; k1++){
            float2 mine = A[k1];
            float2 oth;
            oth.x = __shfl_xor_sync(smask, mine.x, m, 32);
            oth.y = __shfl_xor_sync(smask, mine.y, m, 32);
            if (up) A[k1] = cmul_s<INV>(make_float2(oth.x - mine.x, oth.y - mine.y), w);
            else    A[k1] = make_float2(mine.x + oth.x, mine.y + oth.y);
        }
    }
    if (INV){
        const float s = 1.0f / (float)N;
        #pragma unroll
        for (int k1 = 0; k1 < 7; k1++){ A[k1].x *= s; A[k1].y *= s; }
    }
    #pragma unroll
    for (int k1 = 0; k1 < 7; k1++) a[k1] = A[k1];
}

// ---- legacy line FFT (global-table twiddles) for the pass kernels ----------
template<int LOGG, bool INV>
__device__ __forceinline__ void fft_regs(float2 a[7], int gl){
    const int G  = 1 << LOGG;
    const int N  = 7 * G;
    const int ST = 224 / N;

    float2 w1 = twid<INV>(32), w2 = twid<INV>(64), w3 = twid<INV>(96);
    float2 a0 = a[0];
    float2 s1 = make_float2(a[1].x+a[6].x, a[1].y+a[6].y);
    float2 s2 = make_float2(a[2].x+a[5].x, a[2].y+a[5].y);
    float2 s3 = make_float2(a[3].x+a[4].x, a[3].y+a[4].y);
    float2 d1 = make_float2(a[1].x-a[6].x, a[1].y-a[6].y);
    float2 d2 = make_float2(a[2].x-a[5].x, a[2].y-a[5].y);
    float2 d3 = make_float2(a[3].x-a[4].x, a[3].y-a[4].y);

    float2 A[7];
    A[0] = make_float2(a0.x + s1.x + s2.x + s3.x,
                       a0.y + s1.y + s2.y + s3.y);
    {
        float px = fmaf(w1.x,s1.x, fmaf(w2.x,s2.x, fmaf(w3.x,s3.x, a0.x)));
        float py = fmaf(w1.x,s1.y, fmaf(w2.x,s2.y, fmaf(w3.x,s3.y, a0.y)));
        float qx = fmaf(w1.y,d1.x, fmaf(w2.y,d2.x, w3.y*d3.x));
        float qy = fmaf(w1.y,d1.y, fmaf(w2.y,d2.y, w3.y*d3.y));
        A[1] = make_float2(px - qy, py + qx);
        A[6] = make_float2(px + qy, py - qx);
    }
    {
        float px = fmaf(w2.x,s1.x, fmaf(w3.x,s2.x, fmaf(w1.x,s3.x, a0.x)));
        float py = fmaf(w2.x,s1.y, fmaf(w3.x,s2.y, fmaf(w1.x,s3.y, a0.y)));
        float qx = fmaf(w2.y,d1.x, fmaf(-w3.y,d2.x, -w1.y*d3.x));
        float qy = fmaf(w2.y,d1.y, fmaf(-w3.y,d2.y, -w1.y*d3.y));
        A[2] = make_float2(px - qy, py + qx);
        A[5] = make_float2(px + qy, py - qx);
    }
    {
        float px = fmaf(w3.x,s1.x, fmaf(w1.x,s2.x, fmaf(w2.x,s3.x, a0.x)));
        float py = fmaf(w3.x,s1.y, fmaf(w1.x,s2.y, fmaf(w2.x,s3.y, a0.y)));
        float qx = fmaf(w3.y,d1.x, fmaf(-w1.y,d2.x, w2.y*d3.x));
        float qy = fmaf(w3.y,d1.y, fmaf(-w1.y,d2.y, w2.y*d3.y));
        A[3] = make_float2(px - qy, py + qx);
        A[4] = make_float2(px + qy, py - qx);
    }

    #pragma unroll
    for (int k1 = 1; k1 < 7; k1++)
        A[k1] = cmul(A[k1], twid<INV>(gl * k1 * ST));

    #pragma unroll
    for (int m = G/2; m >= 1; m >>= 1){
        const int tstep = 224 / (2*m);
        float2 w = twid<INV>((gl & (m-1)) * tstep);
        bool up = (gl & m) != 0;
        #pragma unroll
        for (int k1 = 0; k1 < 7; k1++){
            float2 mine = A[k1];
            float2 oth;
            oth.x = __shfl_xor_sync(0xffffffffu, mine.x, m, 32);
            oth.y = __shfl_xor_sync(0xffffffffu, mine.y, m, 32);
            if (up) A[k1] = cmul(make_float2(oth.x - mine.x, oth.y - mine.y), w);
            else    A[k1] = make_float2(mine.x + oth.x, mine.y + oth.y);
        }
    }
    if (INV){
        const float s = 1.0f / (float)N;
        #pragma unroll
        for (int k1 = 0; k1 < 7; k1++){ A[k1].x *= s; A[k1].y *= s; }
    }
    #pragma unroll
    for (int k1 = 0; k1 < 7; k1++) a[k1] = A[k1];
}

__device__ __forceinline__ float blockMax448(float v){
    #pragma unroll
    for (int o = 16; o; o >>= 1) v = fmaxf(v, __shfl_xor_sync(0xffffffffu, v, o));
    __shared__ float red[14];
    int w = threadIdx.x >> 5;
    if ((threadIdx.x & 31) == 0) red[w] = v;
    __syncthreads();
    float m = -FLT_MAX;
    if (threadIdx.x == 0){
        #pragma unroll
        for (int i = 0; i < 14; i++) m = fmaxf(m, red[i]);
    }
    return m;
}

// ---- filter + twiddle + tap generation (every call) ------------------------
__device__ __forceinline__ float ffreq(int a){
    const float PI = 3.14159265358979f;
    return 2.0f*PI*(float)((a < 112) ? a : a - 224) / 224.0f;
}
__global__ void gen_filters_k(){
    int t = blockIdx.x*256 + threadIdx.x;
    const float PI = 3.14159265358979f;
    if (t < 224){
        double ang = -2.0*3.14159265358979323846*(double)t/224.0;
        g_w224[t] = make_float2((float)cos(ang), (float)sin(ang));
        return;
    }
    int u = t - 224;
    if (u < 2*8*IMG224){
        int j = u / (8*IMG224); int r = u - j*(8*IMG224);
        int l = r / IMG224;     int e = r - l*IMG224;
        int aa = e / 224, bb = e - aa*224;
        float wx = ffreq(aa), wy = ffreq(bb);
        float th = (float)l * (PI / 8.0f);
        float xi = (3.0f*PI/4.0f) / (float)(1 << j);
        float sg = 0.8f * (float)(1 << j);
        float ct = cosf(th), st = sinf(th);
        float uu =  ct*wx + st*wy;
        float vv = -st*wx + ct*wy;
        float vs = vv * 2.0f;                // / slant(=0.5)
        float s2 = 0.5f*sg*sg;
        float gab = expf(-s2*((uu-xi)*(uu-xi) + vs*vs));
        float gau = expf(-s2*(uu*uu + vs*vs));
        float kap = expf(-s2*xi*xi);
        float val = gab - kap*gau;
        if (j == 0) g_psi0[l*IMG224 + e] = val;
        else        g_psi1[l*IMG224 + e] = val;
        return;
    }
    u -= 2*8*IMG224;
    if (u < 32){
        int n, stride;
        if (u < 21){ n = u - 10; stride = 1; }              // g_h0 (224 grid)
        else       { n = u - 21 - 5; stride = 2; }          // g_h1 = h0 at even offsets
        float s = 0.f;
        for (int k = 0; k < 224; k++){
            float w = ffreq(k);
            float ang = 2.0f*PI*(float)(k*n*stride)/224.0f;
            s += expf(-1.28f*w*w) * cosf(ang);
        }
        s /= 224.0f;
        if (u < 21) g_h0[u] = s;
        else        g_h1[u-21] = s;
    }
}

// ---- row-mask generation: folded psi1 row alive flags ----------------------
__global__ void gen_mask_k(){
    int t = blockIdx.x*128 + threadIdx.x;   // 8*112 threads
    if (t >= 8*112) return;
    int l = t / 112, b = t - l*112;
    const float* f0 = g_psi1 + (size_t)l*IMG224 +  b       *224;
    const float* f1 = g_psi1 + (size_t)l*IMG224 + (b + 112)*224;
    float mx = 0.f;
    for (int aa = 0; aa < 224; aa++)
        mx = fmaxf(mx, fmaxf(fabsf(f0[aa]), fabsf(f1[aa])));
    g_rowmask[t] = (mx > 1e-4f) ? 1 : 0;
}

// ---- @224 pass: 16 rows/block (512 thr), row FFT + coalesced transposed write
template<int MODE>
__global__ void __launch_bounds__(512) pass224_k(const float* __restrict__ xin){
    constexpr bool IN_REAL  = (MODE == 0);
    constexpr bool MUL_FILT = (MODE == 2);
    constexpr bool INV      = (MODE == 2 || MODE == 3);

    __shared__ float2 sbuf[16][225];
    int i    = blockIdx.y;
    int w    = threadIdx.x >> 5, lane = threadIdx.x & 31;
    int row  = blockIdx.x*16 + w;

    const float* inR = nullptr; const float2* inC = nullptr; const float* filt = nullptr;
    float2* outp = nullptr;
    if constexpr (MODE == 0){ inR = xin + (size_t)i*IMG224;            outp = g_s1buf; }
    if constexpr (MODE == 1){ inC = g_s1buf + (size_t)i*IMG224;        outp = g_xh;    }
    if constexpr (MODE == 2){ inC = g_xh + (size_t)(i >> 3)*IMG224;
                              filt = g_psi0 + (size_t)(i & 7)*IMG224;  outp = g_s1buf; }
    if constexpr (MODE == 3){ inC = g_s1buf + (size_t)i*IMG224;        outp = g_s2buf; }

    float2 a[7];
    #pragma unroll
    for (int n1 = 0; n1 < 7; n1++){
        int idx = row*224 + n1*32 + lane;
        float2 v;
        if constexpr (IN_REAL) v = make_float2(inR[idx], 0.f);
        else                   v = inC[idx];
        if constexpr (MUL_FILT){ float f = filt[idx]; v.x *= f; v.y *= f; }
        a[n1] = v;
    }
    fft_regs<5, INV>(a, lane);

    if constexpr (MODE == 3){
        // modulus (ifft2 complete) -> save spatial u1 (fp16) -> forward FFT
        float* rb = (float*)&sbuf[w][0];
        int k2m = __brev((unsigned)lane) >> 27;
        #pragma unroll
        for (int k1 = 0; k1 < 7; k1++)
            rb[k1 + 7*k2m] = sqrtf(a[k1].x*a[k1].x + a[k1].y*a[k1].y);
        __syncwarp();
        __half* u1o = g_u1h + (size_t)i*IMG224 + row*224;
        #pragma unroll
        for (int n1 = 0; n1 < 7; n1++){
            float v = rb[n1*32 + lane];
            u1o[n1*32 + lane] = __float2half(v);
            a[n1] = make_float2(v, 0.f);
        }
        __syncwarp();
        fft_regs<5, false>(a, lane);
    }

    int k2 = __brev((unsigned)lane) >> 27;
    #pragma unroll
    for (int k1 = 0; k1 < 7; k1++) sbuf[w][k1 + 7*k2] = a[k1];
    __syncthreads();

    int rr   = threadIdx.x & 15;
    int kk   = threadIdx.x >> 4;
    int grow = blockIdx.x*16 + rr;
    float2* o = outp + (size_t)i*IMG224;
    #pragma unroll
    for (int it = 0; it < 7; it++){
        int k = kk + it*32;
        o[k*224 + grow] = sbuf[rr][k];
    }
}

// ---- merged pass4 + second-order fold (coalesced, row-masked) --------------
__global__ void __launch_bounds__(512) pass4fold_k(){
    __shared__ float2 sbuf[16][225];
    int i    = blockIdx.y;
    int w    = threadIdx.x >> 5, lane = threadIdx.x & 31;
    int r0   = blockIdx.x * 8;
    int row  = (w < 8) ? (r0 + w) : (r0 + 112 + (w - 8));

    const float2* inC = g_s2buf + (size_t)i*IMG224;
    float2 a[7];
    #pragma unroll
    for (int n1 = 0; n1 < 7; n1++) a[n1] = inC[row*224 + n1*32 + lane];
    fft_regs<5, false>(a, lane);
    int k2 = __brev((unsigned)lane) >> 27;
    #pragma unroll
    for (int k1 = 0; k1 < 7; k1++) sbuf[w][k1 + 7*k2] = a[k1];
    __syncthreads();

    int outBase = 384 + i*8;
    for (int e = threadIdx.x; e < 896; e += 512){
        int aa = e % 112, bbl = e / 112;
        int b = r0 + bbl;
        float2 z00 = sbuf[bbl    ][aa      ];
        float2 z01 = sbuf[bbl    ][aa + 112];
        float2 z10 = sbuf[bbl + 8][aa      ];
        float2 z11 = sbuf[bbl + 8][aa + 112];
        int f00 =  b       *224 + aa;
        int f10 = (b + 112)*224 + aa;
        #pragma unroll
        for (int l2 = 0; l2 < 8; l2++){
            if (!g_rowmask[l2*112 + b]) continue;       // dead row for this l2
            const float* f = g_psi1 + (size_t)l2*IMG224;
            float v00 = f[f00], v01 = f[f00 + 112], v10 = f[f10], v11 = f[f10 + 112];
            float ax = fmaf(z00.x,v00, fmaf(z01.x,v01, fmaf(z10.x,v10, z11.x*v11)));
            float ay = fmaf(z00.y,v00, fmaf(z01.y,v01, fmaf(z10.y,v10, z11.y*v11)));
            g_foldh[(size_t)(outBase + l2)*IMG112 + b*112 + aa] =
                __floats2half2_rn(ax*0.25f, ay*0.25f);
        }
    }
}

// ---- first-order fold (48 xh sources, all 8 l's, row-masked) ---------------
__global__ void __launch_bounds__(512) fold2_k(){
    int s = blockIdx.y;                     // 0..47
    const float2* src = g_xh + (size_t)s*IMG224;
    int outBase = s*8;
    int base = blockIdx.x*1792;
    for (int e = base + threadIdx.x; e < base + 1792; e += 512){
        int aa = e/112, bb = e - aa*112;
        int i00 =  aa      *224 + bb, i01 =  aa      *224 + bb + 112;
        int i10 = (aa+112) *224 + bb, i11 = (aa+112) *224 + bb + 112;
        float2 s00 = src[i00], s01 = src[i01], s10 = src[i10], s11 = src[i11];
        #pragma unroll
        for (int l2 = 0; l2 < 8; l2++){
            if (!g_rowmask[l2*112 + aa]) continue;      // dead row for this l
            const float* f = g_psi1 + (size_t)l2*IMG224;
            float f00 = f[i00], f01 = f[i01], f10 = f[i10], f11 = f[i11];
            float ax = fmaf(s00.x,f00, fmaf(s01.x,f01, fmaf(s10.x,f10, s11.x*f11)));
            float ay = fmaf(s00.y,f00, fmaf(s01.y,f01, fmaf(s10.y,f10, s11.y*f11)));
            g_foldh[(size_t)(outBase + l2)*IMG112 + e] =
                __floats2half2_rn(ax*0.25f, ay*0.25f);
        }
    }
}

// ---- fused @112 chain (SoA smem, row-masked) -------------------------------
__device__ __forceinline__ void chain112(const __half2* __restrict__ fsrc,
                                         const unsigned char* __restrict__ rmask,
                                         float* featOut){
    extern __shared__ float smf[];
    float* reS = smf;                    // 112 x 115 floats
    float* imS = smf + 112*CPITCH;       // 112 x 115 floats (dead after col pass)
    __shared__ float sh_h[11];
    int tid = threadIdx.x;
    if (tid < 11) sh_h[tid] = g_h1[tid];
    int gl = tid & 15, grp = tid >> 4;   // 28 groups of 16 (half-warps)
    unsigned smask = 0xFFFFu << (tid & 16);   // half-warp shuffle mask

    TW<4> tw; tw.init(gl);               // one twiddle load set, reused 8x

    // ifft2 row pass: masked rows -> zero fill (no load, no FFT)
    for (int r = grp; r < 112; r += 28){
        int k2 = __brev((unsigned)gl) >> 28;
        if (rmask[r]){
            float2 a[7];
            #pragma unroll
            for (int n1 = 0; n1 < 7; n1++)
                a[n1] = __half22float2(fsrc[r*112 + n1*16 + gl]);
            fft_regs_t<4, true>(a, gl, tw, smask);
            #pragma unroll
            for (int k1 = 0; k1 < 7; k1++){
                int p = r*CPITCH + k1 + 7*k2;
                reS[p] = a[k1].x;
                imS[p] = a[k1].y;
            }
        } else {
            #pragma unroll
            for (int k1 = 0; k1 < 7; k1++){
                int p = r*CPITCH + k1 + 7*k2;
                reS[p] = 0.f;
                imS[p] = 0.f;
            }
        }
    }
    __syncthreads();
    // ifft2 col pass: fp32 FFT, modulus -> reS in place (imS becomes dead)
    for (int c = grp; c < 112; c += 28){
        float2 a[7];
        #pragma unroll
        for (int n1 = 0; n1 < 7; n1++){
            int p = (n1*16 + gl)*CPITCH + c;
            a[n1] = make_float2(reS[p], imS[p]);
        }
        fft_regs_t<4, true>(a, gl, tw, smask);
        int k2 = __brev((unsigned)gl) >> 28;
        #pragma unroll
        for (int k1 = 0; k1 < 7; k1++){
            float2 z = a[k1];
            reS[(k1 + 7*k2)*CPITCH + c] = sqrtf(z.x*z.x + z.y*z.y);
        }
    }
    __syncthreads();

    // horizontal blur at stride-2 output cols; hb lives in dead imS
    float* hb = imS;                     // 112 x 57
    #pragma unroll
    for (int it = 0; it < 14; it++){
        int e = tid + it*448;
        int r = e % 112, c = e / 112;
        float acc = 0.f;
        #pragma unroll
        for (int d = 0; d < 11; d++){
            int cc = 2*c + d - 5;
            if (cc < 0) cc += 112; else if (cc >= 112) cc -= 112;
            acc = fmaf(sh_h[d], reS[r*CPITCH + cc], acc);
        }
        hb[r*57 + c] = acc;
    }
    __syncthreads();

    // vertical blur at stride-2 output rows + max
    float mx = -FLT_MAX;
    #pragma unroll
    for (int it = 0; it < 7; it++){
        int e = tid + it*448;
        int a = e / 56, b = e % 56;
        float acc = 0.f;
        #pragma unroll
        for (int d = 0; d < 11; d++){
            int rr = 2*a + d - 5;
            if (rr < 0) rr += 112; else if (rr >= 112) rr -= 112;
            acc = fmaf(sh_h[d], hb[rr*57 + b], acc);
        }
        mx = fmaxf(mx, acc);
    }
    float m = blockMax448(mx);
    if (tid == 0) *featOut = m;
}

// merged j1=1 first order + second order (3456 blocks)
__global__ void __launch_bounds__(448, 2) scatter2_k(){
    int i = blockIdx.x;
    int featIdx;
    if (i < 384){
        int bc = i >> 3, l = i & 7;
        featIdx = bc*81 + 9 + l;
    } else {
        int v = i - 384;
        int bc = v >> 6, l1 = (v >> 3) & 7, l2 = v & 7;
        featIdx = bc*81 + 17 + l1*8 + l2;
    }
    // both branches filter with psi1[i&7] -> same row mask
    chain112(g_foldh + (size_t)i*IMG112, g_rowmask + (i & 7)*112,
             &g_feat[featIdx]);
}

// ---- s0 / s1(j1=0): spatial blur @224, stride 4, circular, + max -----------
__global__ void __launch_bounds__(448) blur224_k(const float* __restrict__ x){
    __shared__ float hb[224*57];        // 51KB
    __shared__ float sh_h[21];
    int i = blockIdx.x;                 // [0,48): s0 from x ; [48,432): s1 j1=0 from u1
    const float* srcF = nullptr; const __half* srcH = nullptr; int featIdx;
    if (i < 48){ srcF = x + (size_t)i*IMG224; featIdx = i*81; }
    else {
        int j = i - 48;
        srcH = g_u1h + (size_t)j*IMG224;
        featIdx = (j >> 3)*81 + 1 + (j & 7);
    }
    int tid = threadIdx.x;
    if (tid < 21) sh_h[tid] = g_h0[tid];
    __syncthreads();

    int rr = tid / 56, c = tid % 56;    // 8 rows x 56 cols per sweep
    for (int r0 = 0; r0 < 224; r0 += 8){
        int r = r0 + rr;
        float acc = 0.f;
        #pragma unroll
        for (int d = 0; d < 21; d++){
            int cc = 4*c + d - 10;
            if (cc < 0) cc += 224; else if (cc >= 224) cc -= 224;
            float v = srcF ? __ldg(srcF + r*224 + cc)
                           : __half2float(srcH[r*224 + cc]);
            acc = fmaf(sh_h[d], v, acc);
        }
        hb[r*57 + c] = acc;
    }
    __syncthreads();

    float mx = -FLT_MAX;
    #pragma unroll
    for (int it = 0; it < 7; it++){
        int e = tid + it*448;
        int a = e / 56, b = e % 56;
        float acc = 0.f;
        #pragma unroll
        for (int d = 0; d < 21; d++){
            int r2 = 4*a + d - 10;
            if (r2 < 0) r2 += 224; else if (r2 >= 224) r2 -= 224;
            acc = fmaf(sh_h[d], hb[r2*57 + b], acc);
        }
        mx = fmaxf(mx, acc);
    }
    float m = blockMax448(mx);
    if (tid == 0) g_feat[featIdx] = m;
}

// ---- final linear ----------------------------------------------------------
__global__ void linear_k(const float* __restrict__ W, const float* __restrict__ bias,
                         float* __restrict__ out){
    __shared__ float gs[243];
    int b = blockIdx.x;
    for (int k = threadIdx.x; k < 243; k += 256) gs[k] = g_feat[b*243 + k];
    __syncthreads();
    for (int o = threadIdx.x; o < 1000; o += 256){
        float acc = bias[o];
        const float* wr = W + o*243;
        #pragma unroll 3
        for (int k = 0; k < 243; k++) acc = fmaf(gs[k], wr[k], acc);
        out[b*1000 + o] = acc;
    }
}

// ---------------------------------------------------------------------------
extern "C" void kernel_launch(void* const* d_in, const int* in_sizes, int n_in,
                              void* d_out, int out_size){
    const float *x = nullptr, *W = nullptr, *bias = nullptr;
    for (int i = 0; i < n_in; i++){
        if      (in_sizes[i] == 16*3*224*224) x    = (const float*)d_in[i];
        else if (in_sizes[i] == 1000*243)     W    = (const float*)d_in[i];
        else if (in_sizes[i] == 1000)         bias = (const float*)d_in[i];
    }
    float* out = (float*)d_out;

    const int SM_CHAIN = 2*112*CPITCH*(int)sizeof(float);  // 103,040 B
    cudaFuncSetAttribute(scatter2_k, cudaFuncAttributeMaxDynamicSharedMemorySize, SM_CHAIN);

    int genTotal = 224 + 2*8*IMG224 + 32;
    gen_filters_k<<<(genTotal + 255)/256, 256>>>();
    gen_mask_k<<<7, 128>>>();                       // 896 threads

    pass224_k<0><<<dim3(14, 48),  512>>>(x);        // x -> s1buf (rows fwd)
    pass224_k<1><<<dim3(14, 48),  512>>>(nullptr);  // s1buf -> xh
    pass224_k<2><<<dim3(14, 384), 512>>>(nullptr);  // xh*psi0 -> s1buf (inv)
    pass224_k<3><<<dim3(14, 384), 512>>>(nullptr);  // inv + |.| -> u1h, fwd -> s2buf

    pass4fold_k<<<dim3(14, 384), 512>>>();          // col FFT + fold*psi1 -> g_foldh
    fold2_k<<<dim3(7, 48), 512>>>();                // first-order folds -> g_foldh
    blur224_k<<<432, 448>>>(x);                     // s0 + s1(j1=0) via spatial blur
    scatter2_k<<<3456, 448, SM_CHAIN>>>();          // s1(j1=1) + s2
    linear_k<<<16, 256>>>(W, bias, out);
    (void)out_size;
}

// round 13
// speedup vs baseline: 1.0212x; 1.0212x over previous
#include <cuda_runtime.h>
#include <cuda_fp16.h>
#include <math.h>
#include <float.h>

// ---------------------------------------------------------------------------
// Scattering2D (J=2, L=8, 224x224) B=16, C=3  + global max pool + linear.
// FFTs: symmetric-pair 7-point DFT per lane x radix-2 shuffle FFT across lanes.
// Low-pass (phi) stages are exact spatial separable Gaussian blurs.
// Second-order fold fused into the final 224-pass (coalesced); fold in fp16.
// @224 passes: TWO independent rows per warp (ILP) -> hides FFT latency chain.
// Chain: SoA fp32 smem (pitch 115, conflict-free), reg-cached twiddles.
// ---------------------------------------------------------------------------

#define IMG224 (224*224)
#define IMG112 (112*112)
#define CPITCH 115                       // chain smem pitch (odd mod 32)
#define PASS_SMEM (32*225*sizeof(float2)) // 57,600 B dynamic smem for passes

// ---- device global scratch -------------------------------------------------
__device__ float2  g_w224[224];
__device__ float   g_psi0[8*IMG224];     // j=0 Morlets @224
__device__ float   g_psi1[8*IMG224];     // j=1 Morlets @224
__device__ float   g_h0[21];             // spatial phi taps @224 (stride-4 path)
__device__ float   g_h1[11];             // spatial phi taps @112 (stride-2 path)
__device__ float2  g_xh[48*IMG224];      // fft2(x)
__device__ float2  g_s1buf[384*IMG224];  // scratch A
__device__ float2  g_s2buf[384*IMG224];  // scratch B
__device__ __half  g_u1h[384*IMG224];    // spatial u1 [TRANSPOSED layout] fp16
__device__ __half2 g_foldh[3456*IMG112]; // prefolded 112x112 chain inputs (fp16)
__device__ float   g_feat[48*81];        // scattering features

// ---- complex helpers -------------------------------------------------------
__device__ __forceinline__ float2 cmul(float2 a, float2 b){
    return make_float2(fmaf(a.x,b.x,-a.y*b.y), fmaf(a.x,b.y, a.y*b.x));
}
template<bool INV>
__device__ __forceinline__ float2 twid(int t){
    float2 w = g_w224[t];
    if (INV) w.y = -w.y;
    return w;
}
template<bool INV>
__device__ __forceinline__ float2 cmul_s(float2 a, float2 b){
    float by = INV ? -b.y : b.y;
    return make_float2(fmaf(a.x,b.x,-a.y*by), fmaf(a.x,by, a.y*b.x));
}

// ---- register-cached twiddles (forward sign; INV conjugates at use) --------
template<int LOGG>
struct TW {
    float2 w1, w2, w3;      // DFT-7 roots
    float2 lt[6];           // lane twiddles k=1..6
    float2 st[LOGG];        // shuffle-stage twiddles
    __device__ __forceinline__ void init(int gl){
        w1 = g_w224[32]; w2 = g_w224[64]; w3 = g_w224[96];
        const int ST = 224 / (7 << LOGG);
        #pragma unroll
        for (int k = 1; k < 7; k++) lt[k-1] = g_w224[gl*k*ST];
        int s = 0;
        #pragma unroll
        for (int m = (1 << LOGG)/2; m >= 1; m >>= 1)
            st[s++] = g_w224[(gl & (m-1)) * (224/(2*m))];
    }
};

// ---- core line FFT with register twiddles (chain) --------------------------
template<int LOGG, bool INV>
__device__ __forceinline__ void fft_regs_t(float2 a[7], int gl, const TW<LOGG>& tw){
    const int G = 1 << LOGG;
    const int N = 7 * G;
    const float sg = INV ? -1.f : 1.f;
    float w1y = sg*tw.w1.y, w2y = sg*tw.w2.y, w3y = sg*tw.w3.y;
    float w1x = tw.w1.x,    w2x = tw.w2.x,    w3x = tw.w3.x;

    float2 a0 = a[0];
    float2 s1 = make_float2(a[1].x+a[6].x, a[1].y+a[6].y);
    float2 s2 = make_float2(a[2].x+a[5].x, a[2].y+a[5].y);
    float2 s3 = make_float2(a[3].x+a[4].x, a[3].y+a[4].y);
    float2 d1 = make_float2(a[1].x-a[6].x, a[1].y-a[6].y);
    float2 d2 = make_float2(a[2].x-a[5].x, a[2].y-a[5].y);
    float2 d3 = make_float2(a[3].x-a[4].x, a[3].y-a[4].y);

    float2 A[7];
    A[0] = make_float2(a0.x + s1.x + s2.x + s3.x,
                       a0.y + s1.y + s2.y + s3.y);
    {
        float px = fmaf(w1x,s1.x, fmaf(w2x,s2.x, fmaf(w3x,s3.x, a0.x)));
        float py = fmaf(w1x,s1.y, fmaf(w2x,s2.y, fmaf(w3x,s3.y, a0.y)));
        float qx = fmaf(w1y,d1.x, fmaf(w2y,d2.x, w3y*d3.x));
        float qy = fmaf(w1y,d1.y, fmaf(w2y,d2.y, w3y*d3.y));
        A[1] = make_float2(px - qy, py + qx);
        A[6] = make_float2(px + qy, py - qx);
    }
    {
        float px = fmaf(w2x,s1.x, fmaf(w3x,s2.x, fmaf(w1x,s3.x, a0.x)));
        float py = fmaf(w2x,s1.y, fmaf(w3x,s2.y, fmaf(w1x,s3.y, a0.y)));
        float qx = fmaf(w2y,d1.x, fmaf(-w3y,d2.x, -w1y*d3.x));
        float qy = fmaf(w2y,d1.y, fmaf(-w3y,d2.y, -w1y*d3.y));
        A[2] = make_float2(px - qy, py + qx);
        A[5] = make_float2(px + qy, py - qx);
    }
    {
        float px = fmaf(w3x,s1.x, fmaf(w1x,s2.x, fmaf(w2x,s3.x, a0.x)));
        float py = fmaf(w3x,s1.y, fmaf(w1x,s2.y, fmaf(w2x,s3.y, a0.y)));
        float qx = fmaf(w3y,d1.x, fmaf(-w1y,d2.x, w2y*d3.x));
        float qy = fmaf(w3y,d1.y, fmaf(-w1y,d2.y, w2y*d3.y));
        A[3] = make_float2(px - qy, py + qx);
        A[4] = make_float2(px + qy, py - qx);
    }

    #pragma unroll
    for (int k1 = 1; k1 < 7; k1++)
        A[k1] = cmul_s<INV>(A[k1], tw.lt[k1-1]);

    int si = 0;
    #pragma unroll
    for (int m = G/2; m >= 1; m >>= 1, si++){
        float2 w = tw.st[si];
        bool up = (gl & m) != 0;
        #pragma unroll
        for (int k1 = 0; k1 < 7; k1++){
            float2 mine = A[k1];
            float2 oth;
            oth.x = __shfl_xor_sync(0xffffffffu, mine.x, m, 32);
            oth.y = __shfl_xor_sync(0xffffffffu, mine.y, m, 32);
            if (up) A[k1] = cmul_s<INV>(make_float2(oth.x - mine.x, oth.y - mine.y), w);
            else    A[k1] = make_float2(mine.x + oth.x, mine.y + oth.y);
        }
    }
    if (INV){
        const float s = 1.0f / (float)N;
        #pragma unroll
        for (int k1 = 0; k1 < 7; k1++){ A[k1].x *= s; A[k1].y *= s; }
    }
    #pragma unroll
    for (int k1 = 0; k1 < 7; k1++) a[k1] = A[k1];
}

// ---- legacy line FFT (global-table twiddles) for the pass kernels ----------
template<int LOGG, bool INV>
__device__ __forceinline__ void fft_regs(float2 a[7], int gl){
    const int G  = 1 << LOGG;
    const int N  = 7 * G;
    const int ST = 224 / N;

    float2 w1 = twid<INV>(32), w2 = twid<INV>(64), w3 = twid<INV>(96);
    float2 a0 = a[0];
    float2 s1 = make_float2(a[1].x+a[6].x, a[1].y+a[6].y);
    float2 s2 = make_float2(a[2].x+a[5].x, a[2].y+a[5].y);
    float2 s3 = make_float2(a[3].x+a[4].x, a[3].y+a[4].y);
    float2 d1 = make_float2(a[1].x-a[6].x, a[1].y-a[6].y);
    float2 d2 = make_float2(a[2].x-a[5].x, a[2].y-a[5].y);
    float2 d3 = make_float2(a[3].x-a[4].x, a[3].y-a[4].y);

    float2 A[7];
    A[0] = make_float2(a0.x + s1.x + s2.x + s3.x,
                       a0.y + s1.y + s2.y + s3.y);
    {
        float px = fmaf(w1.x,s1.x, fmaf(w2.x,s2.x, fmaf(w3.x,s3.x, a0.x)));
        float py = fmaf(w1.x,s1.y, fmaf(w2.x,s2.y, fmaf(w3.x,s3.y, a0.y)));
        float qx = fmaf(w1.y,d1.x, fmaf(w2.y,d2.x, w3.y*d3.x));
        float qy = fmaf(w1.y,d1.y, fmaf(w2.y,d2.y, w3.y*d3.y));
        A[1] = make_float2(px - qy, py + qx);
        A[6] = make_float2(px + qy, py - qx);
    }
    {
        float px = fmaf(w2.x,s1.x, fmaf(w3.x,s2.x, fmaf(w1.x,s3.x, a0.x)));
        float py = fmaf(w2.x,s1.y, fmaf(w3.x,s2.y, fmaf(w1.x,s3.y, a0.y)));
        float qx = fmaf(w2.y,d1.x, fmaf(-w3.y,d2.x, -w1.y*d3.x));
        float qy = fmaf(w2.y,d1.y, fmaf(-w3.y,d2.y, -w1.y*d3.y));
        A[2] = make_float2(px - qy, py + qx);
        A[5] = make_float2(px + qy, py - qx);
    }
    {
        float px = fmaf(w3.x,s1.x, fmaf(w1.x,s2.x, fmaf(w2.x,s3.x, a0.x)));
        float py = fmaf(w3.x,s1.y, fmaf(w1.x,s2.y, fmaf(w2.x,s3.y, a0.y)));
        float qx = fmaf(w3.y,d1.x, fmaf(-w1.y,d2.x, w2.y*d3.x));
        float qy = fmaf(w3.y,d1.y, fmaf(-w1.y,d2.y, w2.y*d3.y));
        A[3] = make_float2(px - qy, py + qx);
        A[4] = make_float2(px + qy, py - qx);
    }

    #pragma unroll
    for (int k1 = 1; k1 < 7; k1++)
        A[k1] = cmul(A[k1], twid<INV>(gl * k1 * ST));

    #pragma unroll
    for (int m = G/2; m >= 1; m >>= 1){
        const int tstep = 224 / (2*m);
        float2 w = twid<INV>((gl & (m-1)) * tstep);
        bool up = (gl & m) != 0;
        #pragma unroll
        for (int k1 = 0; k1 < 7; k1++){
            float2 mine = A[k1];
            float2 oth;
            oth.x = __shfl_xor_sync(0xffffffffu, mine.x, m, 32);
            oth.y = __shfl_xor_sync(0xffffffffu, mine.y, m, 32);
            if (up) A[k1] = cmul(make_float2(oth.x - mine.x, oth.y - mine.y), w);
            else    A[k1] = make_float2(mine.x + oth.x, mine.y + oth.y);
        }
    }
    if (INV){
        const float s = 1.0f / (float)N;
        #pragma unroll
        for (int k1 = 0; k1 < 7; k1++){ A[k1].x *= s; A[k1].y *= s; }
    }
    #pragma unroll
    for (int k1 = 0; k1 < 7; k1++) a[k1] = A[k1];
}

__device__ __forceinline__ float blockMax448(float v){
    #pragma unroll
    for (int o = 16; o; o >>= 1) v = fmaxf(v, __shfl_xor_sync(0xffffffffu, v, o));
    __shared__ float red[14];
    int w = threadIdx.x >> 5;
    if ((threadIdx.x & 31) == 0) red[w] = v;
    __syncthreads();
    float m = -FLT_MAX;
    if (threadIdx.x == 0){
        #pragma unroll
        for (int i = 0; i < 14; i++) m = fmaxf(m, red[i]);
    }
    return m;
}

// ---- filter + twiddle + tap generation (every call) ------------------------
__device__ __forceinline__ float ffreq(int a){
    const float PI = 3.14159265358979f;
    return 2.0f*PI*(float)((a < 112) ? a : a - 224) / 224.0f;
}
__global__ void gen_filters_k(){
    int t = blockIdx.x*256 + threadIdx.x;
    const float PI = 3.14159265358979f;
    if (t < 224){
        double ang = -2.0*3.14159265358979323846*(double)t/224.0;
        g_w224[t] = make_float2((float)cos(ang), (float)sin(ang));
        return;
    }
    int u = t - 224;
    if (u < 2*8*IMG224){
        int j = u / (8*IMG224); int r = u - j*(8*IMG224);
        int l = r / IMG224;     int e = r - l*IMG224;
        int aa = e / 224, bb = e - aa*224;
        float wx = ffreq(aa), wy = ffreq(bb);
        float th = (float)l * (PI / 8.0f);
        float xi = (3.0f*PI/4.0f) / (float)(1 << j);
        float sg = 0.8f * (float)(1 << j);
        float ct = cosf(th), st = sinf(th);
        float uu =  ct*wx + st*wy;
        float vv = -st*wx + ct*wy;
        float vs = vv * 2.0f;                // / slant(=0.5)
        float s2 = 0.5f*sg*sg;
        float gab = expf(-s2*((uu-xi)*(uu-xi) + vs*vs));
        float gau = expf(-s2*(uu*uu + vs*vs));
        float kap = expf(-s2*xi*xi);
        float val = gab - kap*gau;
        if (j == 0) g_psi0[l*IMG224 + e] = val;
        else        g_psi1[l*IMG224 + e] = val;
        return;
    }
    u -= 2*8*IMG224;
    if (u < 32){
        int n, stride;
        if (u < 21){ n = u - 10; stride = 1; }              // g_h0 (224 grid)
        else       { n = u - 21 - 5; stride = 2; }          // g_h1 = h0 at even offsets
        float s = 0.f;
        for (int k = 0; k < 224; k++){
            float w = ffreq(k);
            float ang = 2.0f*PI*(float)(k*n*stride)/224.0f;
            s += expf(-1.28f*w*w) * cosf(ang);
        }
        s /= 224.0f;
        if (u < 21) g_h0[u] = s;
        else        g_h1[u-21] = s;
    }
}

// ---- @224 pass: 32 rows/block, TWO rows per warp (ILP), transposed write ---
// MODE 0: x(real) fwd -> s1buf; 1: s1buf fwd -> xh; 2: xh*psi0 inv -> s1buf;
// MODE 3: inv + |.| -> u1h, fwd -> s2buf
template<int MODE>
__global__ void __launch_bounds__(512) pass224_k(const float* __restrict__ xin){
    constexpr bool IN_REAL  = (MODE == 0);
    constexpr bool MUL_FILT = (MODE == 2);
    constexpr bool INV      = (MODE == 2 || MODE == 3);

    extern __shared__ float2 sbuf[];      // 32 x 225
    int i    = blockIdx.y;
    int w    = threadIdx.x >> 5, lane = threadIdx.x & 31;
    int rowA = blockIdx.x*32 + w*2;
    int rowB = rowA + 1;

    const float* inR = nullptr; const float2* inC = nullptr; const float* filt = nullptr;
    float2* outp = nullptr;
    if constexpr (MODE == 0){ inR = xin + (size_t)i*IMG224;            outp = g_s1buf; }
    if constexpr (MODE == 1){ inC = g_s1buf + (size_t)i*IMG224;        outp = g_xh;    }
    if constexpr (MODE == 2){ inC = g_xh + (size_t)(i >> 3)*IMG224;
                              filt = g_psi0 + (size_t)(i & 7)*IMG224;  outp = g_s1buf; }
    if constexpr (MODE == 3){ inC = g_s1buf + (size_t)i*IMG224;        outp = g_s2buf; }

    float2 a[7], b[7];
    #pragma unroll
    for (int n1 = 0; n1 < 7; n1++){
        int ia = rowA*224 + n1*32 + lane;
        int ib = rowB*224 + n1*32 + lane;
        float2 va, vb;
        if constexpr (IN_REAL){ va = make_float2(inR[ia], 0.f); vb = make_float2(inR[ib], 0.f); }
        else                  { va = inC[ia];                   vb = inC[ib]; }
        if constexpr (MUL_FILT){
            float fa = filt[ia], fb = filt[ib];
            va.x *= fa; va.y *= fa; vb.x *= fb; vb.y *= fb;
        }
        a[n1] = va; b[n1] = vb;
    }
    fft_regs<5, INV>(a, lane);
    fft_regs<5, INV>(b, lane);

    if constexpr (MODE == 3){
        // modulus (ifft2 complete) -> save spatial u1 (fp16) -> forward FFT
        float* rba = (float*)&sbuf[(size_t)(w*2    )*225];
        float* rbb = (float*)&sbuf[(size_t)(w*2 + 1)*225];
        int k2m = __brev((unsigned)lane) >> 27;
        #pragma unroll
        for (int k1 = 0; k1 < 7; k1++){
            rba[k1 + 7*k2m] = sqrtf(a[k1].x*a[k1].x + a[k1].y*a[k1].y);
            rbb[k1 + 7*k2m] = sqrtf(b[k1].x*b[k1].x + b[k1].y*b[k1].y);
        }
        __syncwarp();
        __half* u1a = g_u1h + (size_t)i*IMG224 + rowA*224;
        __half* u1b = g_u1h + (size_t)i*IMG224 + rowB*224;
        #pragma unroll
        for (int n1 = 0; n1 < 7; n1++){
            float va = rba[n1*32 + lane];
            float vb = rbb[n1*32 + lane];
            u1a[n1*32 + lane] = __float2half(va);
            u1b[n1*32 + lane] = __float2half(vb);
            a[n1] = make_float2(va, 0.f);
            b[n1] = make_float2(vb, 0.f);
        }
        __syncwarp();
        fft_regs<5, false>(a, lane);
        fft_regs<5, false>(b, lane);
    }

    int k2 = __brev((unsigned)lane) >> 27;
    #pragma unroll
    for (int k1 = 0; k1 < 7; k1++){
        sbuf[(size_t)(w*2    )*225 + k1 + 7*k2] = a[k1];
        sbuf[(size_t)(w*2 + 1)*225 + k1 + 7*k2] = b[k1];
    }
    __syncthreads();

    // coalesced transposed write: 32 consecutive float2 per warp
    int rr   = threadIdx.x & 31;
    int kk   = threadIdx.x >> 5;         // 16 k-slots
    int grow = blockIdx.x*32 + rr;
    float2* o = outp + (size_t)i*IMG224;
    #pragma unroll
    for (int it = 0; it < 14; it++){
        int k = kk + it*16;
        o[k*224 + grow] = sbuf[(size_t)rr*225 + k];
    }
}

// ---- merged pass4 + second-order fold (pair rows per warp) -----------------
// grid (7, 384). Warp w col-FFTs the conjugate pair (r0+w, r0+112+w) -- exactly
// the pair the 2x2 frequency fold consumes. Coalesced fp16 fold output.
__global__ void __launch_bounds__(512) pass4fold_k(){
    extern __shared__ float2 sbuf[];      // 32 x 225
    int i    = blockIdx.y;
    int w    = threadIdx.x >> 5, lane = threadIdx.x & 31;
    int r0   = blockIdx.x * 16;
    int rowA = r0 + w;                    // w in 0..15
    int rowB = r0 + 112 + w;

    const float2* inC = g_s2buf + (size_t)i*IMG224;
    float2 a[7], b[7];
    #pragma unroll
    for (int n1 = 0; n1 < 7; n1++){
        a[n1] = inC[rowA*224 + n1*32 + lane];
        b[n1] = inC[rowB*224 + n1*32 + lane];
    }
    fft_regs<5, false>(a, lane);
    fft_regs<5, false>(b, lane);
    int k2 = __brev((unsigned)lane) >> 27;
    #pragma unroll
    for (int k1 = 0; k1 < 7; k1++){
        sbuf[(size_t)(w     )*225 + k1 + 7*k2] = a[k1];   // u1h2[r0+w][k]
        sbuf[(size_t)(w + 16)*225 + k1 + 7*k2] = b[k1];   // u1h2[r0+112+w][k]
    }
    __syncthreads();

    int outBase = 384 + i*8;
    for (int e = threadIdx.x; e < 16*112; e += 512){
        int aa = e % 112, bbl = e / 112;
        int bRow = r0 + bbl;
        float2 z00 = sbuf[(size_t)(bbl     )*225 + aa      ];
        float2 z01 = sbuf[(size_t)(bbl     )*225 + aa + 112];
        float2 z10 = sbuf[(size_t)(bbl + 16)*225 + aa      ];
        float2 z11 = sbuf[(size_t)(bbl + 16)*225 + aa + 112];
        int f00 =  bRow       *224 + aa;
        int f10 = (bRow + 112)*224 + aa;
        #pragma unroll
        for (int l2 = 0; l2 < 8; l2++){
            const float* f = g_psi1 + (size_t)l2*IMG224;
            float v00 = f[f00], v01 = f[f00 + 112], v10 = f[f10], v11 = f[f10 + 112];
            float ax = fmaf(z00.x,v00, fmaf(z01.x,v01, fmaf(z10.x,v10, z11.x*v11)));
            float ay = fmaf(z00.y,v00, fmaf(z01.y,v01, fmaf(z10.y,v10, z11.y*v11)));
            g_foldh[(size_t)(outBase + l2)*IMG112 + bRow*112 + aa] =
                __floats2half2_rn(ax*0.25f, ay*0.25f);
        }
    }
}

// ---- first-order fold (48 xh sources, all 8 l's) ---------------------------
__global__ void __launch_bounds__(512) fold2_k(){
    int s = blockIdx.y;                     // 0..47
    const float2* src = g_xh + (size_t)s*IMG224;
    int outBase = s*8;
    int base = blockIdx.x*1792;
    for (int e = base + threadIdx.x; e < base + 1792; e += 512){
        int aa = e/112, bb = e - aa*112;
        int i00 =  aa      *224 + bb, i01 =  aa      *224 + bb + 112;
        int i10 = (aa+112) *224 + bb, i11 = (aa+112) *224 + bb + 112;
        float2 s00 = src[i00], s01 = src[i01], s10 = src[i10], s11 = src[i11];
        #pragma unroll
        for (int l2 = 0; l2 < 8; l2++){
            const float* f = g_psi1 + (size_t)l2*IMG224;
            float f00 = f[i00], f01 = f[i01], f10 = f[i10], f11 = f[i11];
            float ax = fmaf(s00.x,f00, fmaf(s01.x,f01, fmaf(s10.x,f10, s11.x*f11)));
            float ay = fmaf(s00.y,f00, fmaf(s01.y,f01, fmaf(s10.y,f10, s11.y*f11)));
            g_foldh[(size_t)(outBase + l2)*IMG112 + e] =
                __floats2half2_rn(ax*0.25f, ay*0.25f);
        }
    }
}

// ---- fused @112 chain (SoA fp32 smem, pitch 115, conflict-free) ------------
__device__ __forceinline__ void chain112(const __half2* __restrict__ fsrc,
                                         float* featOut){
    extern __shared__ float smf[];
    float* reS = smf;                    // 112 x 115 floats
    float* imS = smf + 112*CPITCH;       // 112 x 115 floats (dead after col pass)
    __shared__ float sh_h[11];
    int tid = threadIdx.x;
    if (tid < 11) sh_h[tid] = g_h1[tid];
    int gl = tid & 15, grp = tid >> 4;   // 28 groups of 16

    TW<4> tw; tw.init(gl);               // one twiddle load set, reused 8x

    // ifft2 row pass: global (fp16) -> fp32 FFT -> SoA smem
    for (int r = grp; r < 112; r += 28){
        float2 a[7];
        #pragma unroll
        for (int n1 = 0; n1 < 7; n1++)
            a[n1] = __half22float2(fsrc[r*112 + n1*16 + gl]);
        fft_regs_t<4, true>(a, gl, tw);
        int k2 = __brev((unsigned)gl) >> 28;
        #pragma unroll
        for (int k1 = 0; k1 < 7; k1++){
            int p = r*CPITCH + k1 + 7*k2;
            reS[p] = a[k1].x;
            imS[p] = a[k1].y;
        }
    }
    __syncthreads();
    // ifft2 col pass: fp32 FFT, modulus -> reS in place (imS becomes dead)
    for (int c = grp; c < 112; c += 28){
        float2 a[7];
        #pragma unroll
        for (int n1 = 0; n1 < 7; n1++){
            int p = (n1*16 + gl)*CPITCH + c;
            a[n1] = make_float2(reS[p], imS[p]);
        }
        fft_regs_t<4, true>(a, gl, tw);
        int k2 = __brev((unsigned)gl) >> 28;
        #pragma unroll
        for (int k1 = 0; k1 < 7; k1++){
            float2 z = a[k1];
            reS[(k1 + 7*k2)*CPITCH + c] = sqrtf(z.x*z.x + z.y*z.y);
        }
    }
    __syncthreads();

    // horizontal blur at stride-2 output cols; hb lives in dead imS
    float* hb = imS;                     // 112 x 57
    #pragma unroll
    for (int it = 0; it < 14; it++){
        int e = tid + it*448;
        int r = e % 112, c = e / 112;
        float acc = 0.f;
        #pragma unroll
        for (int d = 0; d < 11; d++){
            int cc = 2*c + d - 5;
            if (cc < 0) cc += 112; else if (cc >= 112) cc -= 112;
            acc = fmaf(sh_h[d], reS[r*CPITCH + cc], acc);
        }
        hb[r*57 + c] = acc;
    }
    __syncthreads();

    // vertical blur at stride-2 output rows + max
    float mx = -FLT_MAX;
    #pragma unroll
    for (int it = 0; it < 7; it++){
        int e = tid + it*448;
        int a = e / 56, b = e % 56;
        float acc = 0.f;
        #pragma unroll
        for (int d = 0; d < 11; d++){
            int rr = 2*a + d - 5;
            if (rr < 0) rr += 112; else if (rr >= 112) rr -= 112;
            acc = fmaf(sh_h[d], hb[rr*57 + b], acc);
        }
        mx = fmaxf(mx, acc);
    }
    float m = blockMax448(mx);
    if (tid == 0) *featOut = m;
}

// merged j1=1 first order + second order (3456 blocks)
__global__ void __launch_bounds__(448, 2) scatter2_k(){
    int i = blockIdx.x;
    int featIdx;
    if (i < 384){
        int bc = i >> 3, l = i & 7;
        featIdx = bc*81 + 9 + l;
    } else {
        int v = i - 384;
        int bc = v >> 6, l1 = (v >> 3) & 7, l2 = v & 7;
        featIdx = bc*81 + 17 + l1*8 + l2;
    }
    chain112(g_foldh + (size_t)i*IMG112, &g_feat[featIdx]);
}

// ---- s0 / s1(j1=0): spatial blur @224, stride 4, circular, + max -----------
__global__ void __launch_bounds__(448) blur224_k(const float* __restrict__ x){
    __shared__ float hb[224*57];        // 51KB
    __shared__ float sh_h[21];
    int i = blockIdx.x;                 // [0,48): s0 from x ; [48,432): s1 j1=0 from u1
    const float* srcF = nullptr; const __half* srcH = nullptr; int featIdx;
    if (i < 48){ srcF = x + (size_t)i*IMG224; featIdx = i*81; }
    else {
        int j = i - 48;
        srcH = g_u1h + (size_t)j*IMG224;
        featIdx = (j >> 3)*81 + 1 + (j & 7);
    }
    int tid = threadIdx.x;
    if (tid < 21) sh_h[tid] = g_h0[tid];
    __syncthreads();

    int rr = tid / 56, c = tid % 56;    // 8 rows x 56 cols per sweep
    for (int r0 = 0; r0 < 224; r0 += 8){
        int r = r0 + rr;
        float acc = 0.f;
        #pragma unroll
        for (int d = 0; d < 21; d++){
            int cc = 4*c + d - 10;
            if (cc < 0) cc += 224; else if (cc >= 224) cc -= 224;
            float v = srcF ? __ldg(srcF + r*224 + cc)
                           : __half2float(srcH[r*224 + cc]);
            acc = fmaf(sh_h[d], v, acc);
        }
        hb[r*57 + c] = acc;
    }
    __syncthreads();

    float mx = -FLT_MAX;
    #pragma unroll
    for (int it = 0; it < 7; it++){
        int e = tid + it*448;
        int a = e / 56, b = e % 56;
        float acc = 0.f;
        #pragma unroll
        for (int d = 0; d < 21; d++){
            int r2 = 4*a + d - 10;
            if (r2 < 0) r2 += 224; else if (r2 >= 224) r2 -= 224;
            acc = fmaf(sh_h[d], hb[r2*57 + b], acc);
        }
        mx = fmaxf(mx, acc);
    }
    float m = blockMax448(mx);
    if (tid == 0) g_feat[featIdx] = m;
}

// ---- final linear ----------------------------------------------------------
__global__ void linear_k(const float* __restrict__ W, const float* __restrict__ bias,
                         float* __restrict__ out){
    __shared__ float gs[243];
    int b = blockIdx.x;
    for (int k = threadIdx.x; k < 243; k += 256) gs[k] = g_feat[b*243 + k];
    __syncthreads();
    for (int o = threadIdx.x; o < 1000; o += 256){
        float acc = bias[o];
        const float* wr = W + o*243;
        #pragma unroll 3
        for (int k = 0; k < 243; k++) acc = fmaf(gs[k], wr[k], acc);
        out[b*1000 + o] = acc;
    }
}

// ---------------------------------------------------------------------------
extern "C" void kernel_launch(void* const* d_in, const int* in_sizes, int n_in,
                              void* d_out, int out_size){
    const float *x = nullptr, *W = nullptr, *bias = nullptr;
    for (int i = 0; i < n_in; i++){
        if      (in_sizes[i] == 16*3*224*224) x    = (const float*)d_in[i];
        else if (in_sizes[i] == 1000*243)     W    = (const float*)d_in[i];
        else if (in_sizes[i] == 1000)         bias = (const float*)d_in[i];
    }
    float* out = (float*)d_out;

    const int SM_CHAIN = 2*112*CPITCH*(int)sizeof(float);  // 103,040 B
    cudaFuncSetAttribute(scatter2_k, cudaFuncAttributeMaxDynamicSharedMemorySize, SM_CHAIN);
    cudaFuncSetAttribute(pass224_k<0>, cudaFuncAttributeMaxDynamicSharedMemorySize, (int)PASS_SMEM);
    cudaFuncSetAttribute(pass224_k<1>, cudaFuncAttributeMaxDynamicSharedMemorySize, (int)PASS_SMEM);
    cudaFuncSetAttribute(pass224_k<2>, cudaFuncAttributeMaxDynamicSharedMemorySize, (int)PASS_SMEM);
    cudaFuncSetAttribute(pass224_k<3>, cudaFuncAttributeMaxDynamicSharedMemorySize, (int)PASS_SMEM);
    cudaFuncSetAttribute(pass4fold_k,  cudaFuncAttributeMaxDynamicSharedMemorySize, (int)PASS_SMEM);

    int genTotal = 224 + 2*8*IMG224 + 32;
    gen_filters_k<<<(genTotal + 255)/256, 256>>>();

    pass224_k<0><<<dim3(7, 48),  512, PASS_SMEM>>>(x);        // x -> s1buf
    pass224_k<1><<<dim3(7, 48),  512, PASS_SMEM>>>(nullptr);  // s1buf -> xh
    pass224_k<2><<<dim3(7, 384), 512, PASS_SMEM>>>(nullptr);  // xh*psi0 -> s1buf
    pass224_k<3><<<dim3(7, 384), 512, PASS_SMEM>>>(nullptr);  // |.| -> u1h, fwd -> s2buf

    pass4fold_k<<<dim3(7, 384), 512, PASS_SMEM>>>();          // col FFT + fold -> g_foldh
    fold2_k<<<dim3(7, 48), 512>>>();                          // first-order folds
    blur224_k<<<432, 448>>>(x);                               // s0 + s1(j1=0)
    scatter2_k<<<3456, 448, SM_CHAIN>>>();                    // s1(j1=1) + s2
    linear_k<<<16, 256>>>(W, bias, out);
    (void)out_size;
}

// round 14
// speedup vs baseline: 1.0222x; 1.0010x over previous
#include <cuda_runtime.h>
#include <cuda_fp16.h>
#include <math.h>
#include <float.h>

// ---------------------------------------------------------------------------
// Scattering2D (J=2, L=8, 224x224) B=16, C=3  + global max pool + linear.
// FFTs: symmetric-pair 7-point DFT per lane x radix-2 shuffle FFT across lanes.
// Low-pass (phi) stages are exact spatial separable Gaussian blurs.
// Second-order fold fused into the final 224-pass (coalesced); fold in fp16.
// Chain: SoA fp32 smem (pitch 115, conflict-free); TWO interleaved line-FFTs
// per iteration (ILP) with shared twiddle loads.
// ---------------------------------------------------------------------------

#define IMG224 (224*224)
#define IMG112 (112*112)
#define CPITCH 115                       // chain smem pitch (odd mod 32)

// ---- device global scratch -------------------------------------------------
__device__ float2  g_w224[224];
__device__ float   g_psi0[8*IMG224];     // j=0 Morlets @224
__device__ float   g_psi1[8*IMG224];     // j=1 Morlets @224
__device__ float   g_h0[21];             // spatial phi taps @224 (stride-4 path)
__device__ float   g_h1[11];             // spatial phi taps @112 (stride-2 path)
__device__ float2  g_xh[48*IMG224];      // fft2(x)
__device__ float2  g_s1buf[384*IMG224];  // scratch A
__device__ float2  g_s2buf[384*IMG224];  // scratch B
__device__ __half  g_u1h[384*IMG224];    // spatial u1 [TRANSPOSED layout] fp16
__device__ __half2 g_foldh[3456*IMG112]; // prefolded 112x112 chain inputs (fp16)
__device__ float   g_feat[48*81];        // scattering features

// ---- complex helpers -------------------------------------------------------
__device__ __forceinline__ float2 cmul(float2 a, float2 b){
    return make_float2(fmaf(a.x,b.x,-a.y*b.y), fmaf(a.x,b.y, a.y*b.x));
}
template<bool INV>
__device__ __forceinline__ float2 twid(int t){
    float2 w = g_w224[t];
    if (INV) w.y = -w.y;
    return w;
}

// ---- 7-point DFT core (conjugate-pair symmetric form) ----------------------
__device__ __forceinline__ void dft7(float2 a[7],
                                     float w1x, float w1y, float w2x, float w2y,
                                     float w3x, float w3y){
    float2 a0 = a[0];
    float2 s1 = make_float2(a[1].x+a[6].x, a[1].y+a[6].y);
    float2 s2 = make_float2(a[2].x+a[5].x, a[2].y+a[5].y);
    float2 s3 = make_float2(a[3].x+a[4].x, a[3].y+a[4].y);
    float2 d1 = make_float2(a[1].x-a[6].x, a[1].y-a[6].y);
    float2 d2 = make_float2(a[2].x-a[5].x, a[2].y-a[5].y);
    float2 d3 = make_float2(a[3].x-a[4].x, a[3].y-a[4].y);

    a[0] = make_float2(a0.x + s1.x + s2.x + s3.x,
                       a0.y + s1.y + s2.y + s3.y);
    {
        float px = fmaf(w1x,s1.x, fmaf(w2x,s2.x, fmaf(w3x,s3.x, a0.x)));
        float py = fmaf(w1x,s1.y, fmaf(w2x,s2.y, fmaf(w3x,s3.y, a0.y)));
        float qx = fmaf(w1y,d1.x, fmaf(w2y,d2.x, w3y*d3.x));
        float qy = fmaf(w1y,d1.y, fmaf(w2y,d2.y, w3y*d3.y));
        a[1] = make_float2(px - qy, py + qx);
        a[6] = make_float2(px + qy, py - qx);
    }
    {
        float px = fmaf(w2x,s1.x, fmaf(w3x,s2.x, fmaf(w1x,s3.x, a0.x)));
        float py = fmaf(w2x,s1.y, fmaf(w3x,s2.y, fmaf(w1x,s3.y, a0.y)));
        float qx = fmaf(w2y,d1.x, fmaf(-w3y,d2.x, -w1y*d3.x));
        float qy = fmaf(w2y,d1.y, fmaf(-w3y,d2.y, -w1y*d3.y));
        a[2] = make_float2(px - qy, py + qx);
        a[5] = make_float2(px + qy, py - qx);
    }
    {
        float px = fmaf(w3x,s1.x, fmaf(w1x,s2.x, fmaf(w2x,s3.x, a0.x)));
        float py = fmaf(w3x,s1.y, fmaf(w1x,s2.y, fmaf(w2x,s3.y, a0.y)));
        float qx = fmaf(w3y,d1.x, fmaf(-w1y,d2.x, w2y*d3.x));
        float qy = fmaf(w3y,d1.y, fmaf(-w1y,d2.y, w2y*d3.y));
        a[3] = make_float2(px - qy, py + qx);
        a[4] = make_float2(px + qy, py - qx);
    }
}

// ---- single line FFT (pass kernels) ----------------------------------------
template<int LOGG, bool INV>
__device__ __forceinline__ void fft_regs(float2 a[7], int gl){
    const int G  = 1 << LOGG;
    const int N  = 7 * G;
    const int ST = 224 / N;

    float2 w1 = twid<INV>(32), w2 = twid<INV>(64), w3 = twid<INV>(96);
    dft7(a, w1.x, w1.y, w2.x, w2.y, w3.x, w3.y);

    #pragma unroll
    for (int k1 = 1; k1 < 7; k1++)
        a[k1] = cmul(a[k1], twid<INV>(gl * k1 * ST));

    #pragma unroll
    for (int m = G/2; m >= 1; m >>= 1){
        const int tstep = 224 / (2*m);
        float2 w = twid<INV>((gl & (m-1)) * tstep);
        bool up = (gl & m) != 0;
        #pragma unroll
        for (int k1 = 0; k1 < 7; k1++){
            float2 mine = a[k1];
            float2 oth;
            oth.x = __shfl_xor_sync(0xffffffffu, mine.x, m, 32);
            oth.y = __shfl_xor_sync(0xffffffffu, mine.y, m, 32);
            if (up) a[k1] = cmul(make_float2(oth.x - mine.x, oth.y - mine.y), w);
            else    a[k1] = make_float2(mine.x + oth.x, mine.y + oth.y);
        }
    }
    if (INV){
        const float s = 1.0f / (float)N;
        #pragma unroll
        for (int k1 = 0; k1 < 7; k1++){ a[k1].x *= s; a[k1].y *= s; }
    }
}

// ---- paired line FFT: two independent lines, shared twiddle loads (chain) --
template<int LOGG, bool INV>
__device__ __forceinline__ void fft_regs2(float2 a[7], float2 b[7], int gl){
    const int G  = 1 << LOGG;
    const int N  = 7 * G;
    const int ST = 224 / N;

    float2 w1 = twid<INV>(32), w2 = twid<INV>(64), w3 = twid<INV>(96);
    dft7(a, w1.x, w1.y, w2.x, w2.y, w3.x, w3.y);
    dft7(b, w1.x, w1.y, w2.x, w2.y, w3.x, w3.y);

    #pragma unroll
    for (int k1 = 1; k1 < 7; k1++){
        float2 lt = twid<INV>(gl * k1 * ST);
        a[k1] = cmul(a[k1], lt);
        b[k1] = cmul(b[k1], lt);
    }

    #pragma unroll
    for (int m = G/2; m >= 1; m >>= 1){
        const int tstep = 224 / (2*m);
        float2 w = twid<INV>((gl & (m-1)) * tstep);
        bool up = (gl & m) != 0;
        #pragma unroll
        for (int k1 = 0; k1 < 7; k1++){
            float2 ma = a[k1], mb = b[k1];
            float2 oa, ob;
            oa.x = __shfl_xor_sync(0xffffffffu, ma.x, m, 32);
            oa.y = __shfl_xor_sync(0xffffffffu, ma.y, m, 32);
            ob.x = __shfl_xor_sync(0xffffffffu, mb.x, m, 32);
            ob.y = __shfl_xor_sync(0xffffffffu, mb.y, m, 32);
            if (up){
                a[k1] = cmul(make_float2(oa.x - ma.x, oa.y - ma.y), w);
                b[k1] = cmul(make_float2(ob.x - mb.x, ob.y - mb.y), w);
            } else {
                a[k1] = make_float2(ma.x + oa.x, ma.y + oa.y);
                b[k1] = make_float2(mb.x + ob.x, mb.y + ob.y);
            }
        }
    }
    if (INV){
        const float s = 1.0f / (float)N;
        #pragma unroll
        for (int k1 = 0; k1 < 7; k1++){
            a[k1].x *= s; a[k1].y *= s;
            b[k1].x *= s; b[k1].y *= s;
        }
    }
}

__device__ __forceinline__ float blockMax448(float v){
    #pragma unroll
    for (int o = 16; o; o >>= 1) v = fmaxf(v, __shfl_xor_sync(0xffffffffu, v, o));
    __shared__ float red[14];
    int w = threadIdx.x >> 5;
    if ((threadIdx.x & 31) == 0) red[w] = v;
    __syncthreads();
    float m = -FLT_MAX;
    if (threadIdx.x == 0){
        #pragma unroll
        for (int i = 0; i < 14; i++) m = fmaxf(m, red[i]);
    }
    return m;
}

// ---- filter + twiddle + tap generation (every call) ------------------------
__device__ __forceinline__ float ffreq(int a){
    const float PI = 3.14159265358979f;
    return 2.0f*PI*(float)((a < 112) ? a : a - 224) / 224.0f;
}
__global__ void gen_filters_k(){
    int t = blockIdx.x*256 + threadIdx.x;
    const float PI = 3.14159265358979f;
    if (t < 224){
        double ang = -2.0*3.14159265358979323846*(double)t/224.0;
        g_w224[t] = make_float2((float)cos(ang), (float)sin(ang));
        return;
    }
    int u = t - 224;
    if (u < 2*8*IMG224){
        int j = u / (8*IMG224); int r = u - j*(8*IMG224);
        int l = r / IMG224;     int e = r - l*IMG224;
        int aa = e / 224, bb = e - aa*224;
        float wx = ffreq(aa), wy = ffreq(bb);
        float th = (float)l * (PI / 8.0f);
        float xi = (3.0f*PI/4.0f) / (float)(1 << j);
        float sg = 0.8f * (float)(1 << j);
        float ct = cosf(th), st = sinf(th);
        float uu =  ct*wx + st*wy;
        float vv = -st*wx + ct*wy;
        float vs = vv * 2.0f;                // / slant(=0.5)
        float s2 = 0.5f*sg*sg;
        float gab = expf(-s2*((uu-xi)*(uu-xi) + vs*vs));
        float gau = expf(-s2*(uu*uu + vs*vs));
        float kap = expf(-s2*xi*xi);
        float val = gab - kap*gau;
        if (j == 0) g_psi0[l*IMG224 + e] = val;
        else        g_psi1[l*IMG224 + e] = val;
        return;
    }
    u -= 2*8*IMG224;
    if (u < 32){
        int n, stride;
        if (u < 21){ n = u - 10; stride = 1; }              // g_h0 (224 grid)
        else       { n = u - 21 - 5; stride = 2; }          // g_h1 = h0 at even offsets
        float s = 0.f;
        for (int k = 0; k < 224; k++){
            float w = ffreq(k);
            float ang = 2.0f*PI*(float)(k*n*stride)/224.0f;
            s += expf(-1.28f*w*w) * cosf(ang);
        }
        s /= 224.0f;
        if (u < 21) g_h0[u] = s;
        else        g_h1[u-21] = s;
    }
}

// ---- @224 pass: 16 rows/block (512 thr), row FFT + coalesced transposed write
template<int MODE>
__global__ void __launch_bounds__(512) pass224_k(const float* __restrict__ xin){
    constexpr bool IN_REAL  = (MODE == 0);
    constexpr bool MUL_FILT = (MODE == 2);
    constexpr bool INV      = (MODE == 2 || MODE == 3);

    __shared__ float2 sbuf[16][225];
    int i    = blockIdx.y;
    int w    = threadIdx.x >> 5, lane = threadIdx.x & 31;
    int row  = blockIdx.x*16 + w;

    const float* inR = nullptr; const float2* inC = nullptr; const float* filt = nullptr;
    float2* outp = nullptr;
    if constexpr (MODE == 0){ inR = xin + (size_t)i*IMG224;            outp = g_s1buf; }
    if constexpr (MODE == 1){ inC = g_s1buf + (size_t)i*IMG224;        outp = g_xh;    }
    if constexpr (MODE == 2){ inC = g_xh + (size_t)(i >> 3)*IMG224;
                              filt = g_psi0 + (size_t)(i & 7)*IMG224;  outp = g_s1buf; }
    if constexpr (MODE == 3){ inC = g_s1buf + (size_t)i*IMG224;        outp = g_s2buf; }

    float2 a[7];
    #pragma unroll
    for (int n1 = 0; n1 < 7; n1++){
        int idx = row*224 + n1*32 + lane;
        float2 v;
        if constexpr (IN_REAL) v = make_float2(inR[idx], 0.f);
        else                   v = inC[idx];
        if constexpr (MUL_FILT){ float f = filt[idx]; v.x *= f; v.y *= f; }
        a[n1] = v;
    }
    fft_regs<5, INV>(a, lane);

    if constexpr (MODE == 3){
        // modulus (ifft2 complete) -> save spatial u1 (fp16) -> forward FFT
        float* rb = (float*)&sbuf[w][0];
        int k2m = __brev((unsigned)lane) >> 27;
        #pragma unroll
        for (int k1 = 0; k1 < 7; k1++)
            rb[k1 + 7*k2m] = sqrtf(a[k1].x*a[k1].x + a[k1].y*a[k1].y);
        __syncwarp();
        __half* u1o = g_u1h + (size_t)i*IMG224 + row*224;
        #pragma unroll
        for (int n1 = 0; n1 < 7; n1++){
            float v = rb[n1*32 + lane];
            u1o[n1*32 + lane] = __float2half(v);
            a[n1] = make_float2(v, 0.f);
        }
        __syncwarp();
        fft_regs<5, false>(a, lane);
    }

    int k2 = __brev((unsigned)lane) >> 27;
    #pragma unroll
    for (int k1 = 0; k1 < 7; k1++) sbuf[w][k1 + 7*k2] = a[k1];
    __syncthreads();

    int rr   = threadIdx.x & 15;
    int kk   = threadIdx.x >> 4;
    int grow = blockIdx.x*16 + rr;
    float2* o = outp + (size_t)i*IMG224;
    #pragma unroll
    for (int it = 0; it < 7; it++){
        int k = kk + it*32;
        o[k*224 + grow] = sbuf[rr][k];
    }
}

// ---- merged pass4 + second-order fold (coalesced) --------------------------
__global__ void __launch_bounds__(512) pass4fold_k(){
    __shared__ float2 sbuf[16][225];
    int i    = blockIdx.y;
    int w    = threadIdx.x >> 5, lane = threadIdx.x & 31;
    int r0   = blockIdx.x * 8;
    int row  = (w < 8) ? (r0 + w) : (r0 + 112 + (w - 8));

    const float2* inC = g_s2buf + (size_t)i*IMG224;
    float2 a[7];
    #pragma unroll
    for (int n1 = 0; n1 < 7; n1++) a[n1] = inC[row*224 + n1*32 + lane];
    fft_regs<5, false>(a, lane);
    int k2 = __brev((unsigned)lane) >> 27;
    #pragma unroll
    for (int k1 = 0; k1 < 7; k1++) sbuf[w][k1 + 7*k2] = a[k1];
    __syncthreads();

    int outBase = 384 + i*8;
    for (int e = threadIdx.x; e < 896; e += 512){
        int aa = e % 112, bbl = e / 112;
        int b = r0 + bbl;
        float2 z00 = sbuf[bbl    ][aa      ];
        float2 z01 = sbuf[bbl    ][aa + 112];
        float2 z10 = sbuf[bbl + 8][aa      ];
        float2 z11 = sbuf[bbl + 8][aa + 112];
        int f00 =  b       *224 + aa;
        int f10 = (b + 112)*224 + aa;
        #pragma unroll
        for (int l2 = 0; l2 < 8; l2++){
            const float* f = g_psi1 + (size_t)l2*IMG224;
            float v00 = f[f00], v01 = f[f00 + 112], v10 = f[f10], v11 = f[f10 + 112];
            float ax = fmaf(z00.x,v00, fmaf(z01.x,v01, fmaf(z10.x,v10, z11.x*v11)));
            float ay = fmaf(z00.y,v00, fmaf(z01.y,v01, fmaf(z10.y,v10, z11.y*v11)));
            g_foldh[(size_t)(outBase + l2)*IMG112 + b*112 + aa] =
                __floats2half2_rn(ax*0.25f, ay*0.25f);
        }
    }
}

// ---- first-order fold (48 xh sources, all 8 l's) ---------------------------
__global__ void __launch_bounds__(512) fold2_k(){
    int s = blockIdx.y;                     // 0..47
    const float2* src = g_xh + (size_t)s*IMG224;
    int outBase = s*8;
    int base = blockIdx.x*1792;
    for (int e = base + threadIdx.x; e < base + 1792; e += 512){
        int aa = e/112, bb = e - aa*112;
        int i00 =  aa      *224 + bb, i01 =  aa      *224 + bb + 112;
        int i10 = (aa+112) *224 + bb, i11 = (aa+112) *224 + bb + 112;
        float2 s00 = src[i00], s01 = src[i01], s10 = src[i10], s11 = src[i11];
        #pragma unroll
        for (int l2 = 0; l2 < 8; l2++){
            const float* f = g_psi1 + (size_t)l2*IMG224;
            float f00 = f[i00], f01 = f[i01], f10 = f[i10], f11 = f[i11];
            float ax = fmaf(s00.x,f00, fmaf(s01.x,f01, fmaf(s10.x,f10, s11.x*f11)));
            float ay = fmaf(s00.y,f00, fmaf(s01.y,f01, fmaf(s10.y,f10, s11.y*f11)));
            g_foldh[(size_t)(outBase + l2)*IMG112 + e] =
                __floats2half2_rn(ax*0.25f, ay*0.25f);
        }
    }
}

// ---- fused @112 chain (SoA smem, paired-line ILP) --------------------------
__device__ __forceinline__ void chain112(const __half2* __restrict__ fsrc,
                                         float* featOut){
    extern __shared__ float smf[];
    float* reS = smf;                    // 112 x 115 floats
    float* imS = smf + 112*CPITCH;       // 112 x 115 floats (dead after col pass)
    __shared__ float sh_h[11];
    int tid = threadIdx.x;
    if (tid < 11) sh_h[tid] = g_h1[tid];
    int gl = tid & 15, grp = tid >> 4;   // 28 groups of 16

    // ifft2 row pass: 2 interleaved lines per iteration
    #pragma unroll
    for (int half = 0; half < 2; half++){
        int rA = grp + half*28, rB = rA + 56;
        float2 a[7], b[7];
        #pragma unroll
        for (int n1 = 0; n1 < 7; n1++){
            a[n1] = __half22float2(fsrc[rA*112 + n1*16 + gl]);
            b[n1] = __half22float2(fsrc[rB*112 + n1*16 + gl]);
        }
        fft_regs2<4, true>(a, b, gl);
        int k2 = __brev((unsigned)gl) >> 28;
        #pragma unroll
        for (int k1 = 0; k1 < 7; k1++){
            int pA = rA*CPITCH + k1 + 7*k2;
            int pB = rB*CPITCH + k1 + 7*k2;
            reS[pA] = a[k1].x; imS[pA] = a[k1].y;
            reS[pB] = b[k1].x; imS[pB] = b[k1].y;
        }
    }
    __syncthreads();
    // ifft2 col pass: 2 interleaved lines, modulus -> reS in place
    #pragma unroll
    for (int half = 0; half < 2; half++){
        int cA = grp + half*28, cB = cA + 56;
        float2 a[7], b[7];
        #pragma unroll
        for (int n1 = 0; n1 < 7; n1++){
            int rp = (n1*16 + gl)*CPITCH;
            a[n1] = make_float2(reS[rp + cA], imS[rp + cA]);
            b[n1] = make_float2(reS[rp + cB], imS[rp + cB]);
        }
        fft_regs2<4, true>(a, b, gl);
        int k2 = __brev((unsigned)gl) >> 28;
        #pragma unroll
        for (int k1 = 0; k1 < 7; k1++){
            int rp = (k1 + 7*k2)*CPITCH;
            float2 za = a[k1], zb = b[k1];
            reS[rp + cA] = sqrtf(za.x*za.x + za.y*za.y);
            reS[rp + cB] = sqrtf(zb.x*zb.x + zb.y*zb.y);
        }
    }
    __syncthreads();

    // horizontal blur at stride-2 output cols; hb lives in dead imS
    float* hb = imS;                     // 112 x 57
    #pragma unroll
    for (int it = 0; it < 14; it++){
        int e = tid + it*448;
        int r = e % 112, c = e / 112;
        float acc = 0.f;
        #pragma unroll
        for (int d = 0; d < 11; d++){
            int cc = 2*c + d - 5;
            if (cc < 0) cc += 112; else if (cc >= 112) cc -= 112;
            acc = fmaf(sh_h[d], reS[r*CPITCH + cc], acc);
        }
        hb[r*57 + c] = acc;
    }
    __syncthreads();

    // vertical blur at stride-2 output rows + max
    float mx = -FLT_MAX;
    #pragma unroll
    for (int it = 0; it < 7; it++){
        int e = tid + it*448;
        int a = e / 56, b = e % 56;
        float acc = 0.f;
        #pragma unroll
        for (int d = 0; d < 11; d++){
            int rr = 2*a + d - 5;
            if (rr < 0) rr += 112; else if (rr >= 112) rr -= 112;
            acc = fmaf(sh_h[d], hb[rr*57 + b], acc);
        }
        mx = fmaxf(mx, acc);
    }
    float m = blockMax448(mx);
    if (tid == 0) *featOut = m;
}

// merged j1=1 first order + second order (3456 blocks)
__global__ void __launch_bounds__(448, 2) scatter2_k(){
    int i = blockIdx.x;
    int featIdx;
    if (i < 384){
        int bc = i >> 3, l = i & 7;
        featIdx = bc*81 + 9 + l;
    } else {
        int v = i - 384;
        int bc = v >> 6, l1 = (v >> 3) & 7, l2 = v & 7;
        featIdx = bc*81 + 17 + l1*8 + l2;
    }
    chain112(g_foldh + (size_t)i*IMG112, &g_feat[featIdx]);
}

// ---- s0 / s1(j1=0): spatial blur @224, stride 4, circular, + max -----------
__global__ void __launch_bounds__(448) blur224_k(const float* __restrict__ x){
    __shared__ float hb[224*57];        // 51KB
    __shared__ float sh_h[21];
    int i = blockIdx.x;                 // [0,48): s0 from x ; [48,432): s1 j1=0 from u1
    const float* srcF = nullptr; const __half* srcH = nullptr; int featIdx;
    if (i < 48){ srcF = x + (size_t)i*IMG224; featIdx = i*81; }
    else {
        int j = i - 48;
        srcH = g_u1h + (size_t)j*IMG224;
        featIdx = (j >> 3)*81 + 1 + (j & 7);
    }
    int tid = threadIdx.x;
    if (tid < 21) sh_h[tid] = g_h0[tid];
    __syncthreads();

    int rr = tid / 56, c = tid % 56;    // 8 rows x 56 cols per sweep
    for (int r0 = 0; r0 < 224; r0 += 8){
        int r = r0 + rr;
        float acc = 0.f;
        #pragma unroll
        for (int d = 0; d < 21; d++){
            int cc = 4*c + d - 10;
            if (cc < 0) cc += 224; else if (cc >= 224) cc -= 224;
            float v = srcF ? __ldg(srcF + r*224 + cc)
                           : __half2float(srcH[r*224 + cc]);
            acc = fmaf(sh_h[d], v, acc);
        }
        hb[r*57 + c] = acc;
    }
    __syncthreads();

    float mx = -FLT_MAX;
    #pragma unroll
    for (int it = 0; it < 7; it++){
        int e = tid + it*448;
        int a = e / 56, b = e % 56;
        float acc = 0.f;
        #pragma unroll
        for (int d = 0; d < 21; d++){
            int r2 = 4*a + d - 10;
            if (r2 < 0) r2 += 224; else if (r2 >= 224) r2 -= 224;
            acc = fmaf(sh_h[d], hb[r2*57 + b], acc);
        }
        mx = fmaxf(mx, acc);
    }
    float m = blockMax448(mx);
    if (tid == 0) g_feat[featIdx] = m;
}

// ---- final linear ----------------------------------------------------------
__global__ void linear_k(const float* __restrict__ W, const float* __restrict__ bias,
                         float* __restrict__ out){
    __shared__ float gs[243];
    int b = blockIdx.x;
    for (int k = threadIdx.x; k < 243; k += 256) gs[k] = g_feat[b*243 + k];
    __syncthreads();
    for (int o = threadIdx.x; o < 1000; o += 256){
        float acc = bias[o];
        const float* wr = W + o*243;
        #pragma unroll 3
        for (int k = 0; k < 243; k++) acc = fmaf(gs[k], wr[k], acc);
        out[b*1000 + o] = acc;
    }
}

// ---------------------------------------------------------------------------
extern "C" void kernel_launch(void* const* d_in, const int* in_sizes, int n_in,
                              void* d_out, int out_size){
    const float *x = nullptr, *W = nullptr, *bias = nullptr;
    for (int i = 0; i < n_in; i++){
        if      (in_sizes[i] == 16*3*224*224) x    = (const float*)d_in[i];
        else if (in_sizes[i] == 1000*243)     W    = (const float*)d_in[i];
        else if (in_sizes[i] == 1000)         bias = (const float*)d_in[i];
    }
    float* out = (float*)d_out;

    const int SM_CHAIN = 2*112*CPITCH*(int)sizeof(float);  // 103,040 B
    cudaFuncSetAttribute(scatter2_k, cudaFuncAttributeMaxDynamicSharedMemorySize, SM_CHAIN);

    int genTotal = 224 + 2*8*IMG224 + 32;
    gen_filters_k<<<(genTotal + 255)/256, 256>>>();

    pass224_k<0><<<dim3(14, 48),  512>>>(x);        // x -> s1buf (rows fwd)
    pass224_k<1><<<dim3(14, 48),  512>>>(nullptr);  // s1buf -> xh
    pass224_k<2><<<dim3(14, 384), 512>>>(nullptr);  // xh*psi0 -> s1buf (inv)
    pass224_k<3><<<dim3(14, 384), 512>>>(nullptr);  // inv + |.| -> u1h, fwd -> s2buf

    pass4fold_k<<<dim3(14, 384), 512>>>();          // col FFT + fold*psi1 -> g_foldh
    fold2_k<<<dim3(7, 48), 512>>>();                // first-order folds -> g_foldh
    blur224_k<<<432, 448>>>(x);                     // s0 + s1(j1=0) via spatial blur
    scatter2_k<<<3456, 448, SM_CHAIN>>>();          // s1(j1=1) + s2
    linear_k<<<16, 256>>>(W, bias, out);
    (void)out_size;
}

// round 16
// speedup vs baseline: 1.0378x; 1.0152x over previous
#include <cuda_runtime.h>
#include <cuda_fp16.h>
#include <math.h>
#include <float.h>

// ---------------------------------------------------------------------------
// Scattering2D (J=2, L=8, 224x224) B=16, C=3  + global max pool + linear.
// FFTs: symmetric-pair 7-point DFT per lane x radix-2 shuffle FFT across lanes.
// Low-pass (phi) stages are exact spatial separable Gaussian blurs.
// BOTH folds fused into their producing column-FFT passes via conjugate-pair
// rows; first-order fold uses TRANSPOSED psi1 bank (spectrum arrives
// transposed there); fold buffer fp16. Chain transpose-invariant.
// ---------------------------------------------------------------------------

#define IMG224 (224*224)
#define IMG112 (112*112)
#define CPITCH 115                       // chain smem pitch (odd mod 32)

// ---- device global scratch -------------------------------------------------
__device__ float2  g_w224[224];
__device__ float   g_psi0[8*IMG224];     // j=0 Morlets @224
__device__ float   g_psi1[8*IMG224];     // j=1 Morlets @224
__device__ float   g_psi1T[8*IMG224];    // transposed j=1 Morlets
__device__ float   g_h0[21];             // spatial phi taps @224 (stride-4 path)
__device__ float   g_h1[11];             // spatial phi taps @112 (stride-2 path)
__device__ float2  g_xh[48*IMG224];      // fft2(x)
__device__ float2  g_s1buf[384*IMG224];  // scratch A
__device__ float2  g_s2buf[384*IMG224];  // scratch B
__device__ __half  g_u1h[384*IMG224];    // spatial u1 [TRANSPOSED layout] fp16
__device__ __half2 g_foldh[3456*IMG112]; // prefolded 112x112 chain inputs (fp16)
__device__ float   g_feat[48*81];        // scattering features

// ---- complex helpers -------------------------------------------------------
__device__ __forceinline__ float2 cmul(float2 a, float2 b){
    return make_float2(fmaf(a.x,b.x,-a.y*b.y), fmaf(a.x,b.y, a.y*b.x));
}
template<bool INV>
__device__ __forceinline__ float2 twid(int t){
    float2 w = g_w224[t];
    if (INV) w.y = -w.y;
    return w;
}
template<bool INV>
__device__ __forceinline__ float2 cmul_s(float2 a, float2 b){
    float by = INV ? -b.y : b.y;
    return make_float2(fmaf(a.x,b.x,-a.y*by), fmaf(a.x,by, a.y*b.x));
}

// ---- register-cached twiddles (forward sign; INV conjugates at use) --------
template<int LOGG>
struct TW {
    float2 w1, w2, w3;      // DFT-7 roots
    float2 lt[6];           // lane twiddles k=1..6
    float2 st[LOGG];        // shuffle-stage twiddles
    __device__ __forceinline__ void init(int gl){
        w1 = g_w224[32]; w2 = g_w224[64]; w3 = g_w224[96];
        const int ST = 224 / (7 << LOGG);
        #pragma unroll
        for (int k = 1; k < 7; k++) lt[k-1] = g_w224[gl*k*ST];
        int s = 0;
        #pragma unroll
        for (int m = (1 << LOGG)/2; m >= 1; m >>= 1)
            st[s++] = g_w224[(gl & (m-1)) * (224/(2*m))];
    }
};

// ---- core line FFT with register twiddles (chain) --------------------------
template<int LOGG, bool INV>
__device__ __forceinline__ void fft_regs_t(float2 a[7], int gl, const TW<LOGG>& tw){
    const int G = 1 << LOGG;
    const int N = 7 * G;
    const float sg = INV ? -1.f : 1.f;
    float w1y = sg*tw.w1.y, w2y = sg*tw.w2.y, w3y = sg*tw.w3.y;
    float w1x = tw.w1.x,    w2x = tw.w2.x,    w3x = tw.w3.x;

    float2 a0 = a[0];
    float2 s1 = make_float2(a[1].x+a[6].x, a[1].y+a[6].y);
    float2 s2 = make_float2(a[2].x+a[5].x, a[2].y+a[5].y);
    float2 s3 = make_float2(a[3].x+a[4].x, a[3].y+a[4].y);
    float2 d1 = make_float2(a[1].x-a[6].x, a[1].y-a[6].y);
    float2 d2 = make_float2(a[2].x-a[5].x, a[2].y-a[5].y);
    float2 d3 = make_float2(a[3].x-a[4].x, a[3].y-a[4].y);

    float2 A[7];
    A[0] = make_float2(a0.x + s1.x + s2.x + s3.x,
                       a0.y + s1.y + s2.y + s3.y);
    {
        float px = fmaf(w1x,s1.x, fmaf(w2x,s2.x, fmaf(w3x,s3.x, a0.x)));
        float py = fmaf(w1x,s1.y, fmaf(w2x,s2.y, fmaf(w3x,s3.y, a0.y)));
        float qx = fmaf(w1y,d1.x, fmaf(w2y,d2.x, w3y*d3.x));
        float qy = fmaf(w1y,d1.y, fmaf(w2y,d2.y, w3y*d3.y));
        A[1] = make_float2(px - qy, py + qx);
        A[6] = make_float2(px + qy, py - qx);
    }
    {
        float px = fmaf(w2x,s1.x, fmaf(w3x,s2.x, fmaf(w1x,s3.x, a0.x)));
        float py = fmaf(w2x,s1.y, fmaf(w3x,s2.y, fmaf(w1x,s3.y, a0.y)));
        float qx = fmaf(w2y,d1.x, fmaf(-w3y,d2.x, -w1y*d3.x));
        float qy = fmaf(w2y,d1.y, fmaf(-w3y,d2.y, -w1y*d3.y));
        A[2] = make_float2(px - qy, py + qx);
        A[5] = make_float2(px + qy, py - qx);
    }
    {
        float px = fmaf(w3x,s1.x, fmaf(w1x,s2.x, fmaf(w2x,s3.x, a0.x)));
        float py = fmaf(w3x,s1.y, fmaf(w1x,s2.y, fmaf(w2x,s3.y, a0.y)));
        float qx = fmaf(w3y,d1.x, fmaf(-w1y,d2.x, w2y*d3.x));
        float qy = fmaf(w3y,d1.y, fmaf(-w1y,d2.y, w2y*d3.y));
        A[3] = make_float2(px - qy, py + qx);
        A[4] = make_float2(px + qy, py - qx);
    }

    #pragma unroll
    for (int k1 = 1; k1 < 7; k1++)
        A[k1] = cmul_s<INV>(A[k1], tw.lt[k1-1]);

    int si = 0;
    #pragma unroll
    for (int m = G/2; m >= 1; m >>= 1, si++){
        float2 w = tw.st[si];
        bool up = (gl & m) != 0;
        #pragma unroll
        for (int k1 = 0; k1 < 7; k1++){
            float2 mine = A[k1];
            float2 oth;
            oth.x = __shfl_xor_sync(0xffffffffu, mine.x, m, 32);
            oth.y = __shfl_xor_sync(0xffffffffu, mine.y, m, 32);
            if (up) A[k1] = cmul_s<INV>(make_float2(oth.x - mine.x, oth.y - mine.y), w);
            else    A[k1] = make_float2(mine.x + oth.x, mine.y + oth.y);
        }
    }
    if (INV){
        const float s = 1.0f / (float)N;
        #pragma unroll
        for (int k1 = 0; k1 < 7; k1++){ A[k1].x *= s; A[k1].y *= s; }
    }
    #pragma unroll
    for (int k1 = 0; k1 < 7; k1++) a[k1] = A[k1];
}

// ---- legacy line FFT (global-table twiddles) for the pass kernels ----------
template<int LOGG, bool INV>
__device__ __forceinline__ void fft_regs(float2 a[7], int gl){
    const int G  = 1 << LOGG;
    const int N  = 7 * G;
    const int ST = 224 / N;

    float2 w1 = twid<INV>(32), w2 = twid<INV>(64), w3 = twid<INV>(96);
    float2 a0 = a[0];
    float2 s1 = make_float2(a[1].x+a[6].x, a[1].y+a[6].y);
    float2 s2 = make_float2(a[2].x+a[5].x, a[2].y+a[5].y);
    float2 s3 = make_float2(a[3].x+a[4].x, a[3].y+a[4].y);
    float2 d1 = make_float2(a[1].x-a[6].x, a[1].y-a[6].y);
    float2 d2 = make_float2(a[2].x-a[5].x, a[2].y-a[5].y);
    float2 d3 = make_float2(a[3].x-a[4].x, a[3].y-a[4].y);

    float2 A[7];
    A[0] = make_float2(a0.x + s1.x + s2.x + s3.x,
                       a0.y + s1.y + s2.y + s3.y);
    {
        float px = fmaf(w1.x,s1.x, fmaf(w2.x,s2.x, fmaf(w3.x,s3.x, a0.x)));
        float py = fmaf(w1.x,s1.y, fmaf(w2.x,s2.y, fmaf(w3.x,s3.y, a0.y)));
        float qx = fmaf(w1.y,d1.x, fmaf(w2.y,d2.x, w3.y*d3.x));
        float qy = fmaf(w1.y,d1.y, fmaf(w2.y,d2.y, w3.y*d3.y));
        A[1] = make_float2(px - qy, py + qx);
        A[6] = make_float2(px + qy, py - qx);
    }
    {
        float px = fmaf(w2.x,s1.x, fmaf(w3.x,s2.x, fmaf(w1.x,s3.x, a0.x)));
        float py = fmaf(w2.x,s1.y, fmaf(w3.x,s2.y, fmaf(w1.x,s3.y, a0.y)));
        float qx = fmaf(w2.y,d1.x, fmaf(-w3.y,d2.x, -w1.y*d3.x));
        float qy = fmaf(w2.y,d1.y, fmaf(-w3.y,d2.y, -w1.y*d3.y));
        A[2] = make_float2(px - qy, py + qx);
        A[5] = make_float2(px + qy, py - qx);
    }
    {
        float px = fmaf(w3.x,s1.x, fmaf(w1.x,s2.x, fmaf(w2.x,s3.x, a0.x)));
        float py = fmaf(w3.x,s1.y, fmaf(w1.x,s2.y, fmaf(w2.x,s3.y, a0.y)));
        float qx = fmaf(w3.y,d1.x, fmaf(-w1.y,d2.x, w2.y*d3.x));
        float qy = fmaf(w3.y,d1.y, fmaf(-w1.y,d2.y, w2.y*d3.y));
        A[3] = make_float2(px - qy, py + qx);
        A[4] = make_float2(px + qy, py - qx);
    }

    #pragma unroll
    for (int k1 = 1; k1 < 7; k1++)
        A[k1] = cmul(A[k1], twid<INV>(gl * k1 * ST));

    #pragma unroll
    for (int m = G/2; m >= 1; m >>= 1){
        const int tstep = 224 / (2*m);
        float2 w = twid<INV>((gl & (m-1)) * tstep);
        bool up = (gl & m) != 0;
        #pragma unroll
        for (int k1 = 0; k1 < 7; k1++){
            float2 mine = A[k1];
            float2 oth;
            oth.x = __shfl_xor_sync(0xffffffffu, mine.x, m, 32);
            oth.y = __shfl_xor_sync(0xffffffffu, mine.y, m, 32);
            if (up) A[k1] = cmul(make_float2(oth.x - mine.x, oth.y - mine.y), w);
            else    A[k1] = make_float2(mine.x + oth.x, mine.y + oth.y);
        }
    }
    if (INV){
        const float s = 1.0f / (float)N;
        #pragma unroll
        for (int k1 = 0; k1 < 7; k1++){ A[k1].x *= s; A[k1].y *= s; }
    }
    #pragma unroll
    for (int k1 = 0; k1 < 7; k1++) a[k1] = A[k1];
}

__device__ __forceinline__ float blockMax448(float v){
    #pragma unroll
    for (int o = 16; o; o >>= 1) v = fmaxf(v, __shfl_xor_sync(0xffffffffu, v, o));
    __shared__ float red[14];
    int w = threadIdx.x >> 5;
    if ((threadIdx.x & 31) == 0) red[w] = v;
    __syncthreads();
    float m = -FLT_MAX;
    if (threadIdx.x == 0){
        #pragma unroll
        for (int i = 0; i < 14; i++) m = fmaxf(m, red[i]);
    }
    return m;
}

// ---- filter + twiddle + tap generation (every call) ------------------------
__device__ __forceinline__ float ffreq(int a){
    const float PI = 3.14159265358979f;
    return 2.0f*PI*(float)((a < 112) ? a : a - 224) / 224.0f;
}
__global__ void gen_filters_k(){
    int t = blockIdx.x*256 + threadIdx.x;
    const float PI = 3.14159265358979f;
    if (t < 224){
        double ang = -2.0*3.14159265358979323846*(double)t/224.0;
        g_w224[t] = make_float2((float)cos(ang), (float)sin(ang));
        return;
    }
    int u = t - 224;
    if (u < 3*8*IMG224){
        int j = u / (8*IMG224); int r = u - j*(8*IMG224);
        int l = r / IMG224;     int e = r - l*IMG224;
        int aa = e / 224, bb = e - aa*224;
        float wx = ffreq(aa), wy = ffreq(bb);
        if (j == 2){ float tmp = wx; wx = wy; wy = tmp; }   // transposed psi1
        int sj = (j == 0) ? 0 : 1;
        float th = (float)l * (PI / 8.0f);
        float xi = (3.0f*PI/4.0f) / (float)(1 << sj);
        float sg = 0.8f * (float)(1 << sj);
        float ct = cosf(th), st = sinf(th);
        float uu =  ct*wx + st*wy;
        float vv = -st*wx + ct*wy;
        float vs = vv * 2.0f;                // / slant(=0.5)
        float s2 = 0.5f*sg*sg;
        float gab = expf(-s2*((uu-xi)*(uu-xi) + vs*vs));
        float gau = expf(-s2*(uu*uu + vs*vs));
        float kap = expf(-s2*xi*xi);
        float val = gab - kap*gau;
        if (j == 0)      g_psi0 [l*IMG224 + e] = val;
        else if (j == 1) g_psi1 [l*IMG224 + e] = val;
        else             g_psi1T[l*IMG224 + e] = val;
        return;
    }
    u -= 3*8*IMG224;
    if (u < 32){
        int n, stride;
        if (u < 21){ n = u - 10; stride = 1; }              // g_h0 (224 grid)
        else       { n = u - 21 - 5; stride = 2; }          // g_h1 = h0 at even offsets
        float s = 0.f;
        for (int k = 0; k < 224; k++){
            float w = ffreq(k);
            float ang = 2.0f*PI*(float)(k*n*stride)/224.0f;
            s += expf(-1.28f*w*w) * cosf(ang);
        }
        s /= 224.0f;
        if (u < 21) g_h0[u] = s;
        else        g_h1[u-21] = s;
    }
}

// ---- @224 pass: 16 rows/block (512 thr), row FFT + coalesced transposed write
// MODE 0: x(real) fwd -> s1buf; 2: xh*psi0 inv -> s1buf;
// MODE 3: inv + |.| -> u1h, fwd -> s2buf
template<int MODE>
__global__ void __launch_bounds__(512) pass224_k(const float* __restrict__ xin){
    constexpr bool IN_REAL  = (MODE == 0);
    constexpr bool MUL_FILT = (MODE == 2);
    constexpr bool INV      = (MODE == 2 || MODE == 3);

    __shared__ float2 sbuf[16][225];
    int i    = blockIdx.y;
    int w    = threadIdx.x >> 5, lane = threadIdx.x & 31;
    int row  = blockIdx.x*16 + w;

    const float* inR = nullptr; const float2* inC = nullptr; const float* filt = nullptr;
    float2* outp = nullptr;
    if constexpr (MODE == 0){ inR = xin + (size_t)i*IMG224;            outp = g_s1buf; }
    if constexpr (MODE == 2){ inC = g_xh + (size_t)(i >> 3)*IMG224;
                              filt = g_psi0 + (size_t)(i & 7)*IMG224;  outp = g_s1buf; }
    if constexpr (MODE == 3){ inC = g_s1buf + (size_t)i*IMG224;        outp = g_s2buf; }

    float2 a[7];
    #pragma unroll
    for (int n1 = 0; n1 < 7; n1++){
        int idx = row*224 + n1*32 + lane;
        float2 v;
        if constexpr (IN_REAL) v = make_float2(inR[idx], 0.f);
        else                   v = inC[idx];
        if constexpr (MUL_FILT){ float f = filt[idx]; v.x *= f; v.y *= f; }
        a[n1] = v;
    }
    fft_regs<5, INV>(a, lane);

    if constexpr (MODE == 3){
        // modulus (ifft2 complete) -> save spatial u1 (fp16) -> forward FFT
        float* rb = (float*)&sbuf[w][0];
        int k2m = __brev((unsigned)lane) >> 27;
        #pragma unroll
        for (int k1 = 0; k1 < 7; k1++)
            rb[k1 + 7*k2m] = sqrtf(a[k1].x*a[k1].x + a[k1].y*a[k1].y);
        __syncwarp();
        __half* u1o = g_u1h + (size_t)i*IMG224 + row*224;
        #pragma unroll
        for (int n1 = 0; n1 < 7; n1++){
            float v = rb[n1*32 + lane];
            u1o[n1*32 + lane] = __float2half(v);
            a[n1] = make_float2(v, 0.f);
        }
        __syncwarp();
        fft_regs<5, false>(a, lane);
    }

    int k2 = __brev((unsigned)lane) >> 27;
    #pragma unroll
    for (int k1 = 0; k1 < 7; k1++) sbuf[w][k1 + 7*k2] = a[k1];
    __syncthreads();

    int rr   = threadIdx.x & 15;
    int kk   = threadIdx.x >> 4;
    int grow = blockIdx.x*16 + rr;
    float2* o = outp + (size_t)i*IMG224;
    #pragma unroll
    for (int it = 0; it < 7; it++){
        int k = kk + it*32;
        o[k*224 + grow] = sbuf[rr][k];
    }
}

// ---- column FFT + fold, conjugate-pair rows (both orders) ------------------
// FIRST=true : input s1buf (48 imgs), writes xh AND first-order folds (0..383).
//   Here sbuf[w][k] = xh[k_row=k][k_col=line_w] (transposed) -> fold with
//   psi1T (psi1T[b][aa] = psi1[aa][b]); output is the transposed fold, which
//   the chain is invariant to.
// FIRST=false: input s2buf (384 imgs), second-order folds (384..3455); the
//   double transpose through u1 cancels -> fold with psi1 (validated R8+).
template<bool FIRST>
__global__ void __launch_bounds__(512) passfold_k(){
    __shared__ float2 sbuf[16][225];
    int i    = blockIdx.y;
    int w    = threadIdx.x >> 5, lane = threadIdx.x & 31;
    int r0   = blockIdx.x * 8;
    int row  = (w < 8) ? (r0 + w) : (r0 + 112 + (w - 8));

    const float2* inC = (FIRST ? g_s1buf : g_s2buf) + (size_t)i*IMG224;
    float2 a[7];
    #pragma unroll
    for (int n1 = 0; n1 < 7; n1++) a[n1] = inC[row*224 + n1*32 + lane];
    fft_regs<5, false>(a, lane);
    int k2 = __brev((unsigned)lane) >> 27;
    #pragma unroll
    for (int k1 = 0; k1 < 7; k1++) sbuf[w][k1 + 7*k2] = a[k1];
    __syncthreads();

    if constexpr (FIRST){
        // also persist xh in true orientation (consumed by pass224<2>)
        int rr = threadIdx.x & 15;
        int kk = threadIdx.x >> 4;
        int grow = (rr < 8) ? (r0 + rr) : (r0 + 112 + (rr - 8));
        float2* o = g_xh + (size_t)i*IMG224;
        #pragma unroll
        for (int it = 0; it < 7; it++){
            int k = kk + it*32;
            o[k*224 + grow] = sbuf[rr][k];
        }
    }

    const float* bank = FIRST ? g_psi1T : g_psi1;
    int outBase = (FIRST ? 0 : 384) + i*8;
    for (int e = threadIdx.x; e < 896; e += 512){
        int aa = e % 112, bbl = e / 112;
        int b = r0 + bbl;
        float2 z00 = sbuf[bbl    ][aa      ];
        float2 z01 = sbuf[bbl    ][aa + 112];
        float2 z10 = sbuf[bbl + 8][aa      ];
        float2 z11 = sbuf[bbl + 8][aa + 112];
        int f00 =  b       *224 + aa;
        int f10 = (b + 112)*224 + aa;
        #pragma unroll
        for (int l2 = 0; l2 < 8; l2++){
            const float* f = bank + (size_t)l2*IMG224;
            float v00 = f[f00], v01 = f[f00 + 112], v10 = f[f10], v11 = f[f10 + 112];
            float ax = fmaf(z00.x,v00, fmaf(z01.x,v01, fmaf(z10.x,v10, z11.x*v11)));
            float ay = fmaf(z00.y,v00, fmaf(z01.y,v01, fmaf(z10.y,v10, z11.y*v11)));
            g_foldh[(size_t)(outBase + l2)*IMG112 + b*112 + aa] =
                __floats2half2_rn(ax*0.25f, ay*0.25f);
        }
    }
}

// ---- fused @112 chain (SoA fp32 smem, pitch 115, conflict-free) ------------
__device__ __forceinline__ void chain112(const __half2* __restrict__ fsrc,
                                         float* featOut){
    extern __shared__ float smf[];
    float* reS = smf;                    // 112 x 115 floats
    float* imS = smf + 112*CPITCH;       // 112 x 115 floats (dead after col pass)
    __shared__ float sh_h[11];
    int tid = threadIdx.x;
    if (tid < 11) sh_h[tid] = g_h1[tid];
    int gl = tid & 15, grp = tid >> 4;   // 28 groups of 16

    TW<4> tw; tw.init(gl);               // one twiddle load set, reused 8x

    // ifft2 row pass: global (fp16) -> fp32 FFT -> SoA smem
    for (int r = grp; r < 112; r += 28){
        float2 a[7];
        #pragma unroll
        for (int n1 = 0; n1 < 7; n1++)
            a[n1] = __half22float2(fsrc[r*112 + n1*16 + gl]);
        fft_regs_t<4, true>(a, gl, tw);
        int k2 = __brev((unsigned)gl) >> 28;
        #pragma unroll
        for (int k1 = 0; k1 < 7; k1++){
            int p = r*CPITCH + k1 + 7*k2;
            reS[p] = a[k1].x;
            imS[p] = a[k1].y;
        }
    }
    __syncthreads();
    // ifft2 col pass: fp32 FFT, modulus -> reS in place (imS becomes dead)
    for (int c = grp; c < 112; c += 28){
        float2 a[7];
        #pragma unroll
        for (int n1 = 0; n1 < 7; n1++){
            int p = (n1*16 + gl)*CPITCH + c;
            a[n1] = make_float2(reS[p], imS[p]);
        }
        fft_regs_t<4, true>(a, gl, tw);
        int k2 = __brev((unsigned)gl) >> 28;
        #pragma unroll
        for (int k1 = 0; k1 < 7; k1++){
            float2 z = a[k1];
            reS[(k1 + 7*k2)*CPITCH + c] = sqrtf(z.x*z.x + z.y*z.y);
        }
    }
    __syncthreads();

    // horizontal blur at stride-2 output cols; hb lives in dead imS
    float* hb = imS;                     // 112 x 57
    #pragma unroll
    for (int it = 0; it < 14; it++){
        int e = tid + it*448;
        int r = e % 112, c = e / 112;
        float acc = 0.f;
        #pragma unroll
        for (int d = 0; d < 11; d++){
            int cc = 2*c + d - 5;
            if (cc < 0) cc += 112; else if (cc >= 112) cc -= 112;
            acc = fmaf(sh_h[d], reS[r*CPITCH + cc], acc);
        }
        hb[r*57 + c] = acc;
    }
    __syncthreads();

    // vertical blur at stride-2 output rows + max
    float mx = -FLT_MAX;
    #pragma unroll
    for (int it = 0; it < 7; it++){
        int e = tid + it*448;
        int a = e / 56, b = e % 56;
        float acc = 0.f;
        #pragma unroll
        for (int d = 0; d < 11; d++){
            int rr = 2*a + d - 5;
            if (rr < 0) rr += 112; else if (rr >= 112) rr -= 112;
            acc = fmaf(sh_h[d], hb[rr*57 + b], acc);
        }
        mx = fmaxf(mx, acc);
    }
    float m = blockMax448(mx);
    if (tid == 0) *featOut = m;
}

// merged j1=1 first order + second order (3456 blocks)
__global__ void __launch_bounds__(448, 2) scatter2_k(){
    int i = blockIdx.x;
    int featIdx;
    if (i < 384){
        int bc = i >> 3, l = i & 7;
        featIdx = bc*81 + 9 + l;
    } else {
        int v = i - 384;
        int bc = v >> 6, l1 = (v >> 3) & 7, l2 = v & 7;
        featIdx = bc*81 + 17 + l1*8 + l2;
    }
    chain112(g_foldh + (size_t)i*IMG112, &g_feat[featIdx]);
}

// ---- s0 / s1(j1=0): spatial blur @224, stride 4, circular, + max -----------
__global__ void __launch_bounds__(448) blur224_k(const float* __restrict__ x){
    __shared__ float hb[224*57];        // 51KB
    __shared__ float sh_h[21];
    int i = blockIdx.x;                 // [0,48): s0 from x ; [48,432): s1 j1=0 from u1
    const float* srcF = nullptr; const __half* srcH = nullptr; int featIdx;
    if (i < 48){ srcF = x + (size_t)i*IMG224; featIdx = i*81; }
    else {
        int j = i - 48;
        srcH = g_u1h + (size_t)j*IMG224;
        featIdx = (j >> 3)*81 + 1 + (j & 7);
    }
    int tid = threadIdx.x;
    if (tid < 21) sh_h[tid] = g_h0[tid];
    __syncthreads();

    int rr = tid / 56, c = tid % 56;    // 8 rows x 56 cols per sweep
    for (int r0 = 0; r0 < 224; r0 += 8){
        int r = r0 + rr;
        float acc = 0.f;
        #pragma unroll
        for (int d = 0; d < 21; d++){
            int cc = 4*c + d - 10;
            if (cc < 0) cc += 224; else if (cc >= 224) cc -= 224;
            float v = srcF ? __ldg(srcF + r*224 + cc)
                           : __half2float(srcH[r*224 + cc]);
            acc = fmaf(sh_h[d], v, acc);
        }
        hb[r*57 + c] = acc;
    }
    __syncthreads();

    float mx = -FLT_MAX;
    #pragma unroll
    for (int it = 0; it < 7; it++){
        int e = tid + it*448;
        int a = e / 56, b = e % 56;
        float acc = 0.f;
        #pragma unroll
        for (int d = 0; d < 21; d++){
            int r2 = 4*a + d - 10;
            if (r2 < 0) r2 += 224; else if (r2 >= 224) r2 -= 224;
            acc = fmaf(sh_h[d], hb[r2*57 + b], acc);
        }
        mx = fmaxf(mx, acc);
    }
    float m = blockMax448(mx);
    if (tid == 0) g_feat[featIdx] = m;
}

// ---- final linear ----------------------------------------------------------
__global__ void linear_k(const float* __restrict__ W, const float* __restrict__ bias,
                         float* __restrict__ out){
    __shared__ float gs[243];
    int b = blockIdx.x;
    for (int k = threadIdx.x; k < 243; k += 256) gs[k] = g_feat[b*243 + k];
    __syncthreads();
    for (int o = threadIdx.x; o < 1000; o += 256){
        float acc = bias[o];
        const float* wr = W + o*243;
        #pragma unroll 3
        for (int k = 0; k < 243; k++) acc = fmaf(gs[k], wr[k], acc);
        out[b*1000 + o] = acc;
    }
}

// ---------------------------------------------------------------------------
extern "C" void kernel_launch(void* const* d_in, const int* in_sizes, int n_in,
                              void* d_out, int out_size){
    const float *x = nullptr, *W = nullptr, *bias = nullptr;
    for (int i = 0; i < n_in; i++){
        if      (in_sizes[i] == 16*3*224*224) x    = (const float*)d_in[i];
        else if (in_sizes[i] == 1000*243)     W    = (const float*)d_in[i];
        else if (in_sizes[i] == 1000)         bias = (const float*)d_in[i];
    }
    float* out = (float*)d_out;

    const int SM_CHAIN = 2*112*CPITCH*(int)sizeof(float);  // 103,040 B
    cudaFuncSetAttribute(scatter2_k, cudaFuncAttributeMaxDynamicSharedMemorySize, SM_CHAIN);

    int genTotal = 224 + 3*8*IMG224 + 32;
    gen_filters_k<<<(genTotal + 255)/256, 256>>>();

    pass224_k<0><<<dim3(14, 48),  512>>>(x);        // x -> s1buf (rows fwd)
    passfold_k<true><<<dim3(14, 48), 512>>>();      // cols fwd -> xh + 1st-order folds
    pass224_k<2><<<dim3(14, 384), 512>>>(nullptr);  // xh*psi0 -> s1buf (inv)
    pass224_k<3><<<dim3(14, 384), 512>>>(nullptr);  // inv + |.| -> u1h, fwd -> s2buf
    passfold_k<false><<<dim3(14, 384), 512>>>();    // cols fwd + 2nd-order folds

    blur224_k<<<432, 448>>>(x);                     // s0 + s1(j1=0) via spatial blur
    scatter2_k<<<3456, 448, SM_CHAIN>>>();          // s1(j1=1) + s2
    linear_k<<<16, 256>>>(W, bias, out);
    (void)out_size;
}